// round 14
// baseline (speedup 1.0000x reference)
#include <cuda_runtime.h>
#include <cuda_fp16.h>
#include <cstdint>

// Problem constants
#define BATCH 2
#define SEQ 2048
#define HIDDEN 2048
#define NHEADS 32
#define NKV 8
#define HDIM 64
#define KVDIM 512
#define MROWS (BATCH * SEQ)        // 4096
#define NQKV (HIDDEN + 2 * KVDIM)  // 3072

// Scratch (allocation-free rule: __device__ globals), all fp16
__device__ __align__(16) __half g_xh[MROWS * HIDDEN];
__device__ __align__(16) __half g_wqkvh[NQKV * HIDDEN];
__device__ __align__(16) __half g_woh[HIDDEN * HIDDEN];
__device__ __align__(16) __half g_qh[MROWS * HIDDEN];
__device__ __align__(16) __half g_kh[MROWS * KVDIM];
__device__ __align__(16) __half g_vt[BATCH * NKV * HDIM * SEQ];  // [b,kvh,d][s]
__device__ __align__(16) __half g_oh[MROWS * HIDDEN];

__device__ __forceinline__ void mma_f16(float* d, const uint32_t* a, const uint32_t* b) {
    asm volatile(
        "mma.sync.aligned.m16n8k16.row.col.f32.f16.f16.f32 "
        "{%0,%1,%2,%3}, {%4,%5,%6,%7}, {%8,%9}, {%0,%1,%2,%3};"
        : "+f"(d[0]), "+f"(d[1]), "+f"(d[2]), "+f"(d[3])
        : "r"(a[0]), "r"(a[1]), "r"(a[2]), "r"(a[3]), "r"(b[0]), "r"(b[1]));
}

#define LDSM4(r0, r1, r2, r3, addr) \
    asm volatile("ldmatrix.sync.aligned.m8n8.x4.shared.b16 {%0,%1,%2,%3}, [%4];" \
        : "=r"(r0), "=r"(r1), "=r"(r2), "=r"(r3) : "r"(addr))

__device__ __forceinline__ uint32_t smem_u32(const void* p) {
    uint32_t a;
    asm("{ .reg .u64 t; cvta.to.shared.u64 t, %1; cvt.u32.u64 %0, t; }" : "=r"(a) : "l"(p));
    return a;
}

__device__ __forceinline__ void cpasync16(uint32_t dst, const void* src) {
    asm volatile("cp.async.ca.shared.global [%0], [%1], 16;" :: "r"(dst), "l"(src));
}

// ---------------------------------------------------------------------------
// Fused fp32 -> fp16 conversion for all five tensors (single launch)
// ---------------------------------------------------------------------------
#define X4C (MROWS * HIDDEN / 4)
#define Q4C (HIDDEN * HIDDEN / 4)
#define K4C (KVDIM * HIDDEN / 4)
#define TOT4 (X4C + Q4C + 2 * K4C + Q4C)

__global__ void cvt_all(
    const float4* __restrict__ x,  const float4* __restrict__ wq,
    const float4* __restrict__ wk, const float4* __restrict__ wv,
    const float4* __restrict__ wo,
    uint2* __restrict__ xh, uint2* __restrict__ wqkvh, uint2* __restrict__ woh)
{
    int i = blockIdx.x * blockDim.x + threadIdx.x;
    if (i >= TOT4) return;
    float4 v;
    uint2* out;
    if (i < X4C)                      { v = x[i];                      out = xh + i; }
    else if (i < X4C + Q4C)           { int j = i - X4C;               v = wq[j]; out = wqkvh + j; }
    else if (i < X4C + Q4C + K4C)     { int j = i - X4C - Q4C;         v = wk[j]; out = wqkvh + Q4C + j; }
    else if (i < X4C + Q4C + 2 * K4C) { int j = i - X4C - Q4C - K4C;   v = wv[j]; out = wqkvh + Q4C + K4C + j; }
    else                              { int j = i - X4C - Q4C - 2*K4C; v = wo[j]; out = woh + j; }
    __half2 h0 = __floats2half2_rn(v.x, v.y);
    __half2 h1 = __floats2half2_rn(v.z, v.w);
    uint2 o;
    o.x = *(uint32_t*)&h0;
    o.y = *(uint32_t*)&h1;
    *out = o;
}

// ---------------------------------------------------------------------------
// fp16 GEMM core: C[M,N] = A[M,K] @ W[N,K]^T, fp32 accum, ldmatrix fragments.
// CTA tile 64x128, BK=32 (16 uint32/row, stride 20), 256 threads = 8 warps
// (2 wm x 4 wn), warp tile 32x32 -> 32 acc regs/thread, ~70 regs total.
// 3-stage cp.async pipeline, 46 KB smem -> 3 CTAs/SM (24 warps).
// ---------------------------------------------------------------------------
#define GTS 20
#define GA_W (64 * GTS)                       // A region words per stage (1280)
#define GSTAGE_W ((64 + 128) * GTS)           // words per stage (3840)
#define GSM_BYTES (3 * GSTAGE_W * 4)          // 46080

struct GemmCore {
    uint32_t sbase;
    const uint32_t* A;
    const uint32_t* W;
    int K2;
    int bm, bn, tid;

    __device__ __forceinline__ void issue(int kt, int s) {
        const int k0u = kt << 4;              // 16 uint32 per BK=32 tile
        const uint32_t so = (uint32_t)(s * GSTAGE_W);
        // A: 64 rows x 4 uint4 = 256 loads (1/thread)
        {
            int r = tid >> 2, c4 = (tid & 3) * 4;
            uint32_t off = (so + (uint32_t)(r * GTS + c4)) * 4u;
            cpasync16(sbase + off, A + (size_t)(bm + r) * K2 + k0u + c4);
        }
        // B: 128 rows x 4 uint4 = 512 loads (2/thread)
#pragma unroll
        for (int j = 0; j < 2; j++) {
            int idx = j * 256 + tid;
            int r = idx >> 2, c4 = (idx & 3) * 4;
            uint32_t off = (so + (uint32_t)(GA_W + r * GTS + c4)) * 4u;
            cpasync16(sbase + off, W + (size_t)(bn + r) * K2 + k0u + c4);
        }
        asm volatile("cp.async.commit_group;" ::: "memory");
    }

    __device__ __forceinline__ void run(float acc[2][4][4], int wm, int wn, int lane) {
        const uint32_t a_base = sbase +
            (uint32_t)(((wm + (lane & 7) + ((lane >> 3) & 1) * 8) * GTS + ((lane >> 4) & 1) * 4) * 4);
        const uint32_t b_base = sbase + (uint32_t)GA_W * 4u +
            (uint32_t)(((wn + (lane & 7) + ((lane >> 4) & 1) * 8) * GTS + ((lane >> 3) & 1) * 4) * 4);

        const int NT = K2 >> 4;
        issue(0, 0);
        issue(1, 1);
        for (int kt = 0; kt < NT; kt++) {
            if (kt < NT - 1) {
                asm volatile("cp.async.wait_group %0;" :: "n"(1) : "memory");
            } else {
                asm volatile("cp.async.wait_group %0;" :: "n"(0) : "memory");
            }
            __syncthreads();
            if (kt + 2 < NT) issue(kt + 2, (kt + 2) % 3);
            const uint32_t so = (uint32_t)((kt % 3) * GSTAGE_W) * 4u;
#pragma unroll
            for (int kk = 0; kk < 2; kk++) {
                const uint32_t ko = (uint32_t)(kk * 8) * 4u;
                uint32_t af[2][4];
#pragma unroll
                for (int mi = 0; mi < 2; mi++)
                    LDSM4(af[mi][0], af[mi][1], af[mi][2], af[mi][3],
                          a_base + so + ko + (uint32_t)(mi * 16 * GTS) * 4u);
                uint32_t bf[4][2];
#pragma unroll
                for (int p = 0; p < 2; p++)
                    LDSM4(bf[2*p][0], bf[2*p][1], bf[2*p+1][0], bf[2*p+1][1],
                          b_base + so + ko + (uint32_t)(p * 16 * GTS) * 4u);
#pragma unroll
                for (int mi = 0; mi < 2; mi++)
#pragma unroll
                    for (int ni = 0; ni < 4; ni++)
                        mma_f16(acc[mi][ni], af[mi], bf[ni]);
            }
        }
    }
};

// Fused QKV projection; q/k written fp16 row-major, v written fp16 TRANSPOSED.
__global__ __launch_bounds__(256, 3) void gemm_qkv(
    const uint32_t* __restrict__ A, const uint32_t* __restrict__ Wc,
    const float* __restrict__ bq, const float* __restrict__ bk, const float* __restrict__ bv,
    uint32_t* __restrict__ q, uint32_t* __restrict__ k, __half* __restrict__ vt)
{
    extern __shared__ uint32_t sh[];
    const int tid = threadIdx.x;
    const int wid = tid >> 5;
    const int lane = tid & 31;
    const int g = lane >> 2, t = lane & 3;
    const int wm = (wid & 1) * 32, wn = (wid >> 1) * 32;
    const int bm = blockIdx.y * 64, bn = blockIdx.x * 128;

    GemmCore core{smem_u32(sh), A, Wc, HIDDEN / 2, bm, bn, tid};
    float acc[2][4][4] = {};
    core.run(acc, wm, wn, lane);

    if (bn < HIDDEN) {
        const float* bias = bq;
#pragma unroll
        for (int mi = 0; mi < 2; mi++)
#pragma unroll
            for (int ni = 0; ni < 4; ni++) {
                const int col = bn + wn + ni * 8 + 2 * t;
                const float bx = __ldg(bias + col);
                const float by = __ldg(bias + col + 1);
                const int rr0 = bm + wm + mi * 16 + g;
                __half2 h0 = __floats2half2_rn(acc[mi][ni][0] + bx, acc[mi][ni][1] + by);
                __half2 h1 = __floats2half2_rn(acc[mi][ni][2] + bx, acc[mi][ni][3] + by);
                q[(size_t)rr0 * (HIDDEN / 2) + (col >> 1)] = *(uint32_t*)&h0;
                q[(size_t)(rr0 + 8) * (HIDDEN / 2) + (col >> 1)] = *(uint32_t*)&h1;
            }
    } else if (bn < HIDDEN + KVDIM) {
        const float* bias = bk;
        const int cb = bn - HIDDEN;
#pragma unroll
        for (int mi = 0; mi < 2; mi++)
#pragma unroll
            for (int ni = 0; ni < 4; ni++) {
                const int col = cb + wn + ni * 8 + 2 * t;
                const float bx = __ldg(bias + col);
                const float by = __ldg(bias + col + 1);
                const int rr0 = bm + wm + mi * 16 + g;
                __half2 h0 = __floats2half2_rn(acc[mi][ni][0] + bx, acc[mi][ni][1] + by);
                __half2 h1 = __floats2half2_rn(acc[mi][ni][2] + bx, acc[mi][ni][3] + by);
                k[(size_t)rr0 * (KVDIM / 2) + (col >> 1)] = *(uint32_t*)&h0;
                k[(size_t)(rr0 + 8) * (KVDIM / 2) + (col >> 1)] = *(uint32_t*)&h1;
            }
    } else {
        const float* bias = bv;
        const int cb = bn - HIDDEN - KVDIM;
#pragma unroll
        for (int mi = 0; mi < 2; mi++)
#pragma unroll
            for (int ni = 0; ni < 4; ni++) {
                const int col = cb + wn + ni * 8 + 2 * t;   // d index (even)
                const float bx = __ldg(bias + col);
                const float by = __ldg(bias + col + 1);
#pragma unroll
                for (int rr = 0; rr < 2; rr++) {
                    const int row = bm + wm + mi * 16 + g + rr * 8;
                    const int bb = row >> 11;
                    const int s  = row & 2047;
                    const float v0 = acc[mi][ni][rr * 2 + 0] + bx;
                    const float v1 = acc[mi][ni][rr * 2 + 1] + by;
                    const size_t base = ((size_t)(bb * NKV + (col >> 6)) * HDIM);
                    vt[(base + (col & 63)) * SEQ + s]     = __float2half_rn(v0);
                    vt[(base + (col & 63) + 1) * SEQ + s] = __float2half_rn(v1);
                }
            }
    }
}

// O-projection: fp16 inputs, fp32 output + bias.
__global__ __launch_bounds__(256, 3) void gemm_oproj(
    const uint32_t* __restrict__ A, const uint32_t* __restrict__ W,
    const float* __restrict__ bias, float* __restrict__ C)
{
    extern __shared__ uint32_t sh[];
    const int tid = threadIdx.x;
    const int wid = tid >> 5;
    const int lane = tid & 31;
    const int g = lane >> 2, t = lane & 3;
    const int wm = (wid & 1) * 32, wn = (wid >> 1) * 32;
    const int bm = blockIdx.y * 64, bn = blockIdx.x * 128;

    GemmCore core{smem_u32(sh), A, W, HIDDEN / 2, bm, bn, tid};
    float acc[2][4][4] = {};
    core.run(acc, wm, wn, lane);

#pragma unroll
    for (int mi = 0; mi < 2; mi++)
#pragma unroll
        for (int ni = 0; ni < 4; ni++) {
            const int col = bn + wn + ni * 8 + 2 * t;
            const float bx = __ldg(bias + col);
            const float by = __ldg(bias + col + 1);
            const int rr0 = bm + wm + mi * 16 + g;
            float2 v0, v1;
            v0.x = acc[mi][ni][0] + bx; v0.y = acc[mi][ni][1] + by;
            v1.x = acc[mi][ni][2] + bx; v1.y = acc[mi][ni][3] + by;
            *(float2*)(C + (size_t)rr0 * HIDDEN + col) = v0;
            *(float2*)(C + (size_t)(rr0 + 8) * HIDDEN + col) = v1;
        }
}

// ---------------------------------------------------------------------------
// fp16 flash attention: register-resident P, ldmatrix K/V fragments,
// double-buffered cp.async K/Vt tiles. (Validated R11/R12.)
// SMEM (uint32): Qs 128x36 | Ks 2x64x36 | Vt 2x64x36 = 55296 B -> 2 CTAs/SM.
// ---------------------------------------------------------------------------
#define ASM_BYTES ((128 * 36 + 2 * 64 * 36 + 2 * 64 * 36) * 4)

__global__ __launch_bounds__(256, 2) void attn_mma(
    const uint32_t* __restrict__ Qh, const uint32_t* __restrict__ Kh,
    const uint32_t* __restrict__ Vth, uint32_t* __restrict__ Oh)
{
    extern __shared__ uint32_t sm32[];
    uint32_t* Qs = sm32;                     // [128][36] (staging only)
    const uint32_t sbase = smem_u32(sm32);
    const uint32_t ks_off = (uint32_t)(128 * 36) * 4u;
    const uint32_t vt_off = ks_off + 2u * 64u * 36u * 4u;

    const int tid = threadIdx.x;
    const int wid = tid >> 5;
    const int lane = tid & 31;
    const int g = lane >> 2;
    const int t = lane & 3;
    const int qb = blockIdx.x;
    const int h  = blockIdx.y;
    const int b  = blockIdx.z;
    const int kvh = h >> 2;

    const uint32_t* Kbase  = Kh + (size_t)(b * SEQ) * (KVDIM / 2) + kvh * (HDIM / 2);
    const uint32_t* Vtbase = Vth + (size_t)((b * NKV + kvh) * HDIM) * (SEQ / 2);

    const uint32_t bl_off =
        (uint32_t)((((lane & 7) + ((lane >> 4) & 1) * 8) * 36 + ((lane >> 3) & 1) * 4) * 4);

    auto issue = [&](int jb, int s) {
#pragma unroll
        for (int j = 0; j < 2; j++) {
            int idx = j * 256 + tid;
            int r = idx >> 3, c4 = (idx & 7) * 4;
            uint32_t so = (uint32_t)(s * 64 * 36 + r * 36 + c4) * 4u;
            cpasync16(sbase + ks_off + so, Kbase + (size_t)(jb * 64 + r) * (KVDIM / 2) + c4);
            cpasync16(sbase + vt_off + so, Vtbase + (size_t)r * (SEQ / 2) + jb * 32 + c4);
        }
        asm volatile("cp.async.commit_group;" ::: "memory");
    };

    issue(0, 0);

    // Stage Q tile (coalesced), scale by 1/8
    {
        const __half2 sc = __float2half2_rn(0.125f);
        const uint32_t* src = Qh + (size_t)(b * SEQ + qb * 128) * (HIDDEN / 2) + h * (HDIM / 2);
#pragma unroll
        for (int j = 0; j < 4; j++) {
            int idx = j * 256 + tid;
            int r = idx >> 3, c = (idx & 7) * 4;
            uint4 v = *(const uint4*)(src + (size_t)r * (HIDDEN / 2) + c);
            __half2* hp = (__half2*)&v;
            hp[0] = __hmul2(hp[0], sc); hp[1] = __hmul2(hp[1], sc);
            hp[2] = __hmul2(hp[2], sc); hp[3] = __hmul2(hp[3], sc);
            uint32_t* dst = &Qs[r * 36 + c];
            dst[0] = v.x; dst[1] = v.y; dst[2] = v.z; dst[3] = v.w;
        }
    }
    __syncthreads();

    const int qr = wid * 16 + g;
    uint32_t qf[4][4];
#pragma unroll
    for (int kk = 0; kk < 4; kk++) {
        const int kc = kk * 8 + t;
        qf[kk][0] = Qs[qr * 36 + kc];
        qf[kk][1] = Qs[(qr + 8) * 36 + kc];
        qf[kk][2] = Qs[qr * 36 + kc + 4];
        qf[kk][3] = Qs[(qr + 8) * 36 + kc + 4];
    }

    float acc_o[8][4] = {};
    float m0 = -1e30f, m1 = -1e30f, l0 = 0.f, l1 = 0.f;

    for (int jb = 0; jb < SEQ / 64; jb++) {
        const int s = jb & 1;
        if (jb + 1 < SEQ / 64) {
            issue(jb + 1, s ^ 1);
            asm volatile("cp.async.wait_group %0;" :: "n"(1) : "memory");
        } else {
            asm volatile("cp.async.wait_group %0;" :: "n"(0) : "memory");
        }
        __syncthreads();

        const uint32_t kf_base = sbase + ks_off + (uint32_t)(s * 64 * 36) * 4u + bl_off;
        const uint32_t vf_base = sbase + vt_off + (uint32_t)(s * 64 * 36) * 4u + bl_off;

        // S = Q K^T
        float acc_s[8][4] = {};
#pragma unroll
        for (int kk = 0; kk < 4; kk++) {
            const uint32_t ko = (uint32_t)(kk * 8) * 4u;
#pragma unroll
            for (int p = 0; p < 4; p++) {
                uint32_t bf[4];
                LDSM4(bf[0], bf[1], bf[2], bf[3], kf_base + ko + (uint32_t)(p * 16 * 36) * 4u);
                mma_f16(acc_s[2*p],     qf[kk], bf);
                mma_f16(acc_s[2*p + 1], qf[kk], bf + 2);
            }
        }

        // Fragment online softmax
        float mx0 = -1e30f, mx1 = -1e30f;
#pragma unroll
        for (int ni = 0; ni < 8; ni++) {
            mx0 = fmaxf(mx0, fmaxf(acc_s[ni][0], acc_s[ni][1]));
            mx1 = fmaxf(mx1, fmaxf(acc_s[ni][2], acc_s[ni][3]));
        }
        mx0 = fmaxf(mx0, __shfl_xor_sync(0xffffffffu, mx0, 1));
        mx0 = fmaxf(mx0, __shfl_xor_sync(0xffffffffu, mx0, 2));
        mx1 = fmaxf(mx1, __shfl_xor_sync(0xffffffffu, mx1, 1));
        mx1 = fmaxf(mx1, __shfl_xor_sync(0xffffffffu, mx1, 2));
        const float mn0 = fmaxf(m0, mx0);
        const float mn1 = fmaxf(m1, mx1);
        const float sf0 = __expf(m0 - mn0);
        const float sf1 = __expf(m1 - mn1);
        m0 = mn0; m1 = mn1;

#pragma unroll
        for (int dn = 0; dn < 8; dn++) {
            acc_o[dn][0] *= sf0; acc_o[dn][1] *= sf0;
            acc_o[dn][2] *= sf1; acc_o[dn][3] *= sf1;
        }

        // P = exp(S - m): pack directly into PV A-fragments
        uint32_t pf[4][4];
        float rs0 = 0.f, rs1 = 0.f;
#pragma unroll
        for (int kb = 0; kb < 4; kb++) {
#pragma unroll
            for (int half = 0; half < 2; half++) {
                const int ni = 2 * kb + half;
                float p0 = __expf(acc_s[ni][0] - mn0);
                float p1 = __expf(acc_s[ni][1] - mn0);
                float p2 = __expf(acc_s[ni][2] - mn1);
                float p3 = __expf(acc_s[ni][3] - mn1);
                rs0 += p0 + p1;
                rs1 += p2 + p3;
                __half2 w0 = __floats2half2_rn(p0, p1);
                __half2 w1 = __floats2half2_rn(p2, p3);
                pf[kb][half * 2 + 0] = *(uint32_t*)&w0;
                pf[kb][half * 2 + 1] = *(uint32_t*)&w1;
            }
        }
        rs0 += __shfl_xor_sync(0xffffffffu, rs0, 1);
        rs0 += __shfl_xor_sync(0xffffffffu, rs0, 2);
        rs1 += __shfl_xor_sync(0xffffffffu, rs1, 1);
        rs1 += __shfl_xor_sync(0xffffffffu, rs1, 2);
        l0 = l0 * sf0 + rs0;
        l1 = l1 * sf1 + rs1;

        // O += P V
#pragma unroll
        for (int kb = 0; kb < 4; kb++) {
            const uint32_t ko = (uint32_t)(kb * 8) * 4u;
#pragma unroll
            for (int p = 0; p < 4; p++) {
                uint32_t bf[4];
                LDSM4(bf[0], bf[1], bf[2], bf[3], vf_base + ko + (uint32_t)(p * 16 * 36) * 4u);
                mma_f16(acc_o[2*p],     pf[kb], bf);
                mma_f16(acc_o[2*p + 1], pf[kb], bf + 2);
            }
        }
        __syncthreads();
    }

    // Epilogue: normalize, store fp16 (feeds O-proj mma)
    const float i0 = 1.f / l0;
    const float i1 = 1.f / l1;
    const int row0 = b * SEQ + qb * 128 + qr;
#pragma unroll
    for (int dn = 0; dn < 8; dn++) {
        const int cp = h * (HDIM / 2) + dn * 4 + t;
        __half2 h0 = __floats2half2_rn(acc_o[dn][0] * i0, acc_o[dn][1] * i0);
        __half2 h1 = __floats2half2_rn(acc_o[dn][2] * i1, acc_o[dn][3] * i1);
        Oh[(size_t)row0 * (HIDDEN / 2) + cp] = *(uint32_t*)&h0;
        Oh[(size_t)(row0 + 8) * (HIDDEN / 2) + cp] = *(uint32_t*)&h1;
    }
}

// ---------------------------------------------------------------------------
extern "C" void kernel_launch(void* const* d_in, const int* in_sizes, int n_in,
                              void* d_out, int out_size)
{
    const float* x  = (const float*)d_in[0];
    const float* wq = (const float*)d_in[1];
    const float* bq = (const float*)d_in[2];
    const float* wk = (const float*)d_in[3];
    const float* bk = (const float*)d_in[4];
    const float* wv = (const float*)d_in[5];
    const float* bv = (const float*)d_in[6];
    const float* wo = (const float*)d_in[7];
    const float* bo = (const float*)d_in[8];
    float* out = (float*)d_out;

    __half *xh, *wqkvh, *woh, *qh, *kh, *vt, *oh;
    cudaGetSymbolAddress((void**)&xh, g_xh);
    cudaGetSymbolAddress((void**)&wqkvh, g_wqkvh);
    cudaGetSymbolAddress((void**)&woh, g_woh);
    cudaGetSymbolAddress((void**)&qh, g_qh);
    cudaGetSymbolAddress((void**)&kh, g_kh);
    cudaGetSymbolAddress((void**)&vt, g_vt);
    cudaGetSymbolAddress((void**)&oh, g_oh);

    cudaFuncSetAttribute(gemm_qkv,   cudaFuncAttributeMaxDynamicSharedMemorySize, GSM_BYTES);
    cudaFuncSetAttribute(gemm_oproj, cudaFuncAttributeMaxDynamicSharedMemorySize, GSM_BYTES);
    cudaFuncSetAttribute(attn_mma,   cudaFuncAttributeMaxDynamicSharedMemorySize, ASM_BYTES);

    cvt_all<<<(TOT4 + 255) / 256, 256>>>(
        (const float4*)x, (const float4*)wq, (const float4*)wk,
        (const float4*)wv, (const float4*)wo,
        (uint2*)xh, (uint2*)wqkvh, (uint2*)woh);

    gemm_qkv<<<dim3(NQKV / 128, MROWS / 64), 256, GSM_BYTES>>>(
        (const uint32_t*)xh, (const uint32_t*)wqkvh, bq, bk, bv,
        (uint32_t*)qh, (uint32_t*)kh, vt);

    attn_mma<<<dim3(SEQ / 128, NHEADS, BATCH), 256, ASM_BYTES>>>(
        (const uint32_t*)qh, (const uint32_t*)kh, (const uint32_t*)vt, (uint32_t*)oh);

    gemm_oproj<<<dim3(HIDDEN / 128, MROWS / 64), 256, GSM_BYTES>>>(
        (const uint32_t*)oh, (const uint32_t*)woh, bo, out);
}

// round 15
// speedup vs baseline: 1.0235x; 1.0235x over previous
#include <cuda_runtime.h>
#include <cuda_fp16.h>
#include <cstdint>

// Problem constants
#define BATCH 2
#define SEQ 2048
#define HIDDEN 2048
#define NHEADS 32
#define NKV 8
#define HDIM 64
#define KVDIM 512
#define MROWS (BATCH * SEQ)        // 4096
#define NQKV (HIDDEN + 2 * KVDIM)  // 3072

// Scratch (allocation-free rule: __device__ globals), all fp16
__device__ __align__(16) __half g_xh[MROWS * HIDDEN];
__device__ __align__(16) __half g_wqkvh[NQKV * HIDDEN];
__device__ __align__(16) __half g_woh[HIDDEN * HIDDEN];
__device__ __align__(16) __half g_qh[MROWS * HIDDEN];
__device__ __align__(16) __half g_kh[MROWS * KVDIM];
__device__ __align__(16) __half g_vt[BATCH * NKV * HDIM * SEQ];  // [b,kvh,d][s]
__device__ __align__(16) __half g_oh[MROWS * HIDDEN];

__device__ __forceinline__ void mma_f16(float* d, const uint32_t* a, const uint32_t* b) {
    asm volatile(
        "mma.sync.aligned.m16n8k16.row.col.f32.f16.f16.f32 "
        "{%0,%1,%2,%3}, {%4,%5,%6,%7}, {%8,%9}, {%0,%1,%2,%3};"
        : "+f"(d[0]), "+f"(d[1]), "+f"(d[2]), "+f"(d[3])
        : "r"(a[0]), "r"(a[1]), "r"(a[2]), "r"(a[3]), "r"(b[0]), "r"(b[1]));
}

#define LDSM4(r0, r1, r2, r3, addr) \
    asm volatile("ldmatrix.sync.aligned.m8n8.x4.shared.b16 {%0,%1,%2,%3}, [%4];" \
        : "=r"(r0), "=r"(r1), "=r"(r2), "=r"(r3) : "r"(addr))

__device__ __forceinline__ uint32_t smem_u32(const void* p) {
    uint32_t a;
    asm("{ .reg .u64 t; cvta.to.shared.u64 t, %1; cvt.u32.u64 %0, t; }" : "=r"(a) : "l"(p));
    return a;
}

__device__ __forceinline__ void cpasync16(uint32_t dst, const void* src) {
    asm volatile("cp.async.ca.shared.global [%0], [%1], 16;" :: "r"(dst), "l"(src));
}

// ---------------------------------------------------------------------------
// Fused fp32 -> fp16 conversion for all five tensors (single launch)
// ---------------------------------------------------------------------------
#define X4C (MROWS * HIDDEN / 4)
#define Q4C (HIDDEN * HIDDEN / 4)
#define K4C (KVDIM * HIDDEN / 4)
#define TOT4 (X4C + Q4C + 2 * K4C + Q4C)

__global__ void cvt_all(
    const float4* __restrict__ x,  const float4* __restrict__ wq,
    const float4* __restrict__ wk, const float4* __restrict__ wv,
    const float4* __restrict__ wo,
    uint2* __restrict__ xh, uint2* __restrict__ wqkvh, uint2* __restrict__ woh)
{
    int i = blockIdx.x * blockDim.x + threadIdx.x;
    if (i >= TOT4) return;
    float4 v;
    uint2* out;
    if (i < X4C)                      { v = x[i];                      out = xh + i; }
    else if (i < X4C + Q4C)           { int j = i - X4C;               v = wq[j]; out = wqkvh + j; }
    else if (i < X4C + Q4C + K4C)     { int j = i - X4C - Q4C;         v = wk[j]; out = wqkvh + Q4C + j; }
    else if (i < X4C + Q4C + 2 * K4C) { int j = i - X4C - Q4C - K4C;   v = wv[j]; out = wqkvh + Q4C + K4C + j; }
    else                              { int j = i - X4C - Q4C - 2*K4C; v = wo[j]; out = woh + j; }
    __half2 h0 = __floats2half2_rn(v.x, v.y);
    __half2 h1 = __floats2half2_rn(v.z, v.w);
    uint2 o;
    o.x = *(uint32_t*)&h0;
    o.y = *(uint32_t*)&h1;
    *out = o;
}

// ---------------------------------------------------------------------------
// fp16 GEMM core (REVERTED to R12 best config): C = A @ W^T, fp32 accum.
// CTA 128x128, BK=64 (32 uint32/row, stride 36), 256 threads (8 warps 2x4),
// warp tile 64x32, 3-stage cp.async. SMEM 110592 B -> 2 CTAs/SM.
// ---------------------------------------------------------------------------
#define GTS 36
#define GSTAGE_W (128 * GTS)
#define GB_OFF_W (3 * GSTAGE_W)
#define GSM_BYTES (2 * 3 * GSTAGE_W * 4)     // 110592

struct GemmCore {
    uint32_t sbase;
    const uint32_t* A;
    const uint32_t* W;
    int K2;
    int bm, bn, tid;

    __device__ __forceinline__ void issue(int kt, int s) {
        const int k0u = kt << 5;
        const uint32_t so = (uint32_t)(s * GSTAGE_W);
#pragma unroll
        for (int j = 0; j < 4; j++) {
            int idx = j * 256 + tid;
            int r = idx >> 3, c4 = (idx & 7) * 4;
            uint32_t off = (so + (uint32_t)(r * GTS + c4)) * 4u;
            cpasync16(sbase + off, A + (size_t)(bm + r) * K2 + k0u + c4);
            cpasync16(sbase + off + (uint32_t)GB_OFF_W * 4u, W + (size_t)(bn + r) * K2 + k0u + c4);
        }
        asm volatile("cp.async.commit_group;" ::: "memory");
    }

    __device__ __forceinline__ void run(float acc[4][4][4], int wm, int wn, int lane) {
        const uint32_t a_base = sbase +
            (uint32_t)(((wm + (lane & 7) + ((lane >> 3) & 1) * 8) * GTS + ((lane >> 4) & 1) * 4) * 4);
        const uint32_t b_base = sbase + (uint32_t)GB_OFF_W * 4u +
            (uint32_t)(((wn + (lane & 7) + ((lane >> 4) & 1) * 8) * GTS + ((lane >> 3) & 1) * 4) * 4);

        const int NT = K2 >> 5;
        issue(0, 0);
        issue(1, 1);
        for (int kt = 0; kt < NT; kt++) {
            if (kt < NT - 1) {
                asm volatile("cp.async.wait_group %0;" :: "n"(1) : "memory");
            } else {
                asm volatile("cp.async.wait_group %0;" :: "n"(0) : "memory");
            }
            __syncthreads();
            if (kt + 2 < NT) issue(kt + 2, (kt + 2) % 3);
            const uint32_t so = (uint32_t)((kt % 3) * GSTAGE_W) * 4u;
#pragma unroll
            for (int kk = 0; kk < 4; kk++) {
                const uint32_t ko = (uint32_t)(kk * 8) * 4u;
                uint32_t af[4][4];
#pragma unroll
                for (int mi = 0; mi < 4; mi++)
                    LDSM4(af[mi][0], af[mi][1], af[mi][2], af[mi][3],
                          a_base + so + ko + (uint32_t)(mi * 16 * GTS) * 4u);
                uint32_t bf[4][2];
#pragma unroll
                for (int p = 0; p < 2; p++)
                    LDSM4(bf[2*p][0], bf[2*p][1], bf[2*p+1][0], bf[2*p+1][1],
                          b_base + so + ko + (uint32_t)(p * 16 * GTS) * 4u);
#pragma unroll
                for (int mi = 0; mi < 4; mi++)
#pragma unroll
                    for (int ni = 0; ni < 4; ni++)
                        mma_f16(acc[mi][ni], af[mi], bf[ni]);
            }
        }
    }
};

// Fused QKV projection; q/k written fp16 row-major, v written fp16 TRANSPOSED.
__global__ __launch_bounds__(256, 2) void gemm_qkv(
    const uint32_t* __restrict__ A, const uint32_t* __restrict__ Wc,
    const float* __restrict__ bq, const float* __restrict__ bk, const float* __restrict__ bv,
    uint32_t* __restrict__ q, uint32_t* __restrict__ k, __half* __restrict__ vt)
{
    extern __shared__ uint32_t sh[];
    const int tid = threadIdx.x;
    const int wid = tid >> 5;
    const int lane = tid & 31;
    const int g = lane >> 2, t = lane & 3;
    const int wm = (wid & 1) * 64, wn = (wid >> 1) * 32;
    const int bm = blockIdx.y * 128, bn = blockIdx.x * 128;

    GemmCore core{smem_u32(sh), A, Wc, HIDDEN / 2, bm, bn, tid};
    float acc[4][4][4] = {};
    core.run(acc, wm, wn, lane);

    if (bn < HIDDEN) {
        const float* bias = bq;
#pragma unroll
        for (int mi = 0; mi < 4; mi++)
#pragma unroll
            for (int ni = 0; ni < 4; ni++) {
                const int col = bn + wn + ni * 8 + 2 * t;
                const float bx = __ldg(bias + col);
                const float by = __ldg(bias + col + 1);
                const int rr0 = bm + wm + mi * 16 + g;
                __half2 h0 = __floats2half2_rn(acc[mi][ni][0] + bx, acc[mi][ni][1] + by);
                __half2 h1 = __floats2half2_rn(acc[mi][ni][2] + bx, acc[mi][ni][3] + by);
                q[(size_t)rr0 * (HIDDEN / 2) + (col >> 1)] = *(uint32_t*)&h0;
                q[(size_t)(rr0 + 8) * (HIDDEN / 2) + (col >> 1)] = *(uint32_t*)&h1;
            }
    } else if (bn < HIDDEN + KVDIM) {
        const float* bias = bk;
        const int cb = bn - HIDDEN;
#pragma unroll
        for (int mi = 0; mi < 4; mi++)
#pragma unroll
            for (int ni = 0; ni < 4; ni++) {
                const int col = cb + wn + ni * 8 + 2 * t;
                const float bx = __ldg(bias + col);
                const float by = __ldg(bias + col + 1);
                const int rr0 = bm + wm + mi * 16 + g;
                __half2 h0 = __floats2half2_rn(acc[mi][ni][0] + bx, acc[mi][ni][1] + by);
                __half2 h1 = __floats2half2_rn(acc[mi][ni][2] + bx, acc[mi][ni][3] + by);
                k[(size_t)rr0 * (KVDIM / 2) + (col >> 1)] = *(uint32_t*)&h0;
                k[(size_t)(rr0 + 8) * (KVDIM / 2) + (col >> 1)] = *(uint32_t*)&h1;
            }
    } else {
        const float* bias = bv;
        const int cb = bn - HIDDEN - KVDIM;
#pragma unroll
        for (int mi = 0; mi < 4; mi++)
#pragma unroll
            for (int ni = 0; ni < 4; ni++) {
                const int col = cb + wn + ni * 8 + 2 * t;   // d index (even)
                const float bx = __ldg(bias + col);
                const float by = __ldg(bias + col + 1);
#pragma unroll
                for (int rr = 0; rr < 2; rr++) {
                    const int row = bm + wm + mi * 16 + g + rr * 8;
                    const int bb = row >> 11;
                    const int s  = row & 2047;
                    const float v0 = acc[mi][ni][rr * 2 + 0] + bx;
                    const float v1 = acc[mi][ni][rr * 2 + 1] + by;
                    const size_t base = ((size_t)(bb * NKV + (col >> 6)) * HDIM);
                    vt[(base + (col & 63)) * SEQ + s]     = __float2half_rn(v0);
                    vt[(base + (col & 63) + 1) * SEQ + s] = __float2half_rn(v1);
                }
            }
    }
}

// O-projection: fp16 inputs, fp32 output + bias.
__global__ __launch_bounds__(256, 2) void gemm_oproj(
    const uint32_t* __restrict__ A, const uint32_t* __restrict__ W,
    const float* __restrict__ bias, float* __restrict__ C)
{
    extern __shared__ uint32_t sh[];
    const int tid = threadIdx.x;
    const int wid = tid >> 5;
    const int lane = tid & 31;
    const int g = lane >> 2, t = lane & 3;
    const int wm = (wid & 1) * 64, wn = (wid >> 1) * 32;
    const int bm = blockIdx.y * 128, bn = blockIdx.x * 128;

    GemmCore core{smem_u32(sh), A, W, HIDDEN / 2, bm, bn, tid};
    float acc[4][4][4] = {};
    core.run(acc, wm, wn, lane);

#pragma unroll
    for (int mi = 0; mi < 4; mi++)
#pragma unroll
        for (int ni = 0; ni < 4; ni++) {
            const int col = bn + wn + ni * 8 + 2 * t;
            const float bx = __ldg(bias + col);
            const float by = __ldg(bias + col + 1);
            const int rr0 = bm + wm + mi * 16 + g;
            float2 v0, v1;
            v0.x = acc[mi][ni][0] + bx; v0.y = acc[mi][ni][1] + by;
            v1.x = acc[mi][ni][2] + bx; v1.y = acc[mi][ni][3] + by;
            *(float2*)(C + (size_t)rr0 * HIDDEN + col) = v0;
            *(float2*)(C + (size_t)(rr0 + 8) * HIDDEN + col) = v1;
        }
}

// ---------------------------------------------------------------------------
// GQA-aware fp16 flash attention: one CTA serves ALL 4 query heads of a KV
// group (K/V loaded once per group instead of 4x -> 4x less tile traffic).
// CTA = (b, kvh, 64-query tile). 512 threads = 16 warps:
//   wid>>2 = head-in-group (0-3), wid&3 = 16-row subtile within the 64 rows.
// Per-warp inner loop identical to validated R11 version (register P,
// ldmatrix K/V fragments, double-buffered cp.async K/Vt).
// SMEM (words): Qs 64x132 | Ks 2x64x36 | Vt 2x64x36 = 70656 B. 1 CTA/SM.
// ---------------------------------------------------------------------------
#define AQS_W (64 * 132)
#define AKV_W (64 * 36)
#define ASM_BYTES ((AQS_W + 4 * AKV_W) * 4)   // 70656

__global__ __launch_bounds__(512, 1) void attn_mma(
    const uint32_t* __restrict__ Qh, const uint32_t* __restrict__ Kh,
    const uint32_t* __restrict__ Vth, uint32_t* __restrict__ Oh)
{
    extern __shared__ uint32_t sm32[];
    uint32_t* Qs = sm32;                     // [64][132] (4 heads x 32 u32 cols)
    const uint32_t sbase = smem_u32(sm32);
    const uint32_t ks_off = (uint32_t)AQS_W * 4u;
    const uint32_t vt_off = ks_off + 2u * (uint32_t)AKV_W * 4u;

    const int tid = threadIdx.x;
    const int wid = tid >> 5;
    const int lane = tid & 31;
    const int g = lane >> 2;
    const int t = lane & 3;
    const int qb  = blockIdx.x;              // 0..31 (64-row q tiles)
    const int kvh = blockIdx.y;              // 0..7
    const int b   = blockIdx.z;
    const int hh  = wid >> 2;                // head in group 0..3
    const int ws  = wid & 3;                 // row subtile 0..3
    const int h   = kvh * 4 + hh;

    const uint32_t* Kbase  = Kh + (size_t)(b * SEQ) * (KVDIM / 2) + kvh * (HDIM / 2);
    const uint32_t* Vtbase = Vth + (size_t)((b * NKV + kvh) * HDIM) * (SEQ / 2);

    const uint32_t bl_off =
        (uint32_t)((((lane & 7) + ((lane >> 4) & 1) * 8) * 36 + ((lane >> 3) & 1) * 4) * 4);

    // K/Vt tile load: 512 ops K + 512 ops V; 1 uint4 each per thread.
    auto issue = [&](int jb, int s) {
        int r = tid >> 3, c4 = (tid & 7) * 4;
        uint32_t so = (uint32_t)(s * AKV_W + r * 36 + c4) * 4u;
        cpasync16(sbase + ks_off + so, Kbase + (size_t)(jb * 64 + r) * (KVDIM / 2) + c4);
        cpasync16(sbase + vt_off + so, Vtbase + (size_t)r * (SEQ / 2) + jb * 32 + c4);
        asm volatile("cp.async.commit_group;" ::: "memory");
    };

    issue(0, 0);

    // Stage Q tile: 64 rows x 128 u32 (4 heads contiguous), scale by 1/8.
    {
        const __half2 sc = __float2half2_rn(0.125f);
        const uint32_t* src = Qh + (size_t)(b * SEQ + qb * 64) * (HIDDEN / 2) + kvh * 128;
#pragma unroll
        for (int j = 0; j < 4; j++) {
            int idx = j * 512 + tid;
            int r = idx >> 5, c = (idx & 31) * 4;
            uint4 v = *(const uint4*)(src + (size_t)r * (HIDDEN / 2) + c);
            __half2* hp = (__half2*)&v;
            hp[0] = __hmul2(hp[0], sc); hp[1] = __hmul2(hp[1], sc);
            hp[2] = __hmul2(hp[2], sc); hp[3] = __hmul2(hp[3], sc);
            uint32_t* dst = &Qs[r * 132 + c];
            dst[0] = v.x; dst[1] = v.y; dst[2] = v.z; dst[3] = v.w;
        }
    }
    __syncthreads();

    // Hoist Q fragments (loop-invariant). Row within tile: ws*16 + g.
    const int qr = ws * 16 + g;
    const int qc0 = hh * 32;                 // this head's u32 column base
    uint32_t qf[4][4];
#pragma unroll
    for (int kk = 0; kk < 4; kk++) {
        const int kc = qc0 + kk * 8 + t;
        qf[kk][0] = Qs[qr * 132 + kc];
        qf[kk][1] = Qs[(qr + 8) * 132 + kc];
        qf[kk][2] = Qs[qr * 132 + kc + 4];
        qf[kk][3] = Qs[(qr + 8) * 132 + kc + 4];
    }

    float acc_o[8][4] = {};
    float m0 = -1e30f, m1 = -1e30f, l0 = 0.f, l1 = 0.f;

    for (int jb = 0; jb < SEQ / 64; jb++) {
        const int s = jb & 1;
        if (jb + 1 < SEQ / 64) {
            issue(jb + 1, s ^ 1);
            asm volatile("cp.async.wait_group %0;" :: "n"(1) : "memory");
        } else {
            asm volatile("cp.async.wait_group %0;" :: "n"(0) : "memory");
        }
        __syncthreads();

        const uint32_t kf_base = sbase + ks_off + (uint32_t)(s * AKV_W) * 4u + bl_off;
        const uint32_t vf_base = sbase + vt_off + (uint32_t)(s * AKV_W) * 4u + bl_off;

        // S = Q K^T
        float acc_s[8][4] = {};
#pragma unroll
        for (int kk = 0; kk < 4; kk++) {
            const uint32_t ko = (uint32_t)(kk * 8) * 4u;
#pragma unroll
            for (int p = 0; p < 4; p++) {
                uint32_t bf[4];
                LDSM4(bf[0], bf[1], bf[2], bf[3], kf_base + ko + (uint32_t)(p * 16 * 36) * 4u);
                mma_f16(acc_s[2*p],     qf[kk], bf);
                mma_f16(acc_s[2*p + 1], qf[kk], bf + 2);
            }
        }

        // Fragment online softmax
        float mx0 = -1e30f, mx1 = -1e30f;
#pragma unroll
        for (int ni = 0; ni < 8; ni++) {
            mx0 = fmaxf(mx0, fmaxf(acc_s[ni][0], acc_s[ni][1]));
            mx1 = fmaxf(mx1, fmaxf(acc_s[ni][2], acc_s[ni][3]));
        }
        mx0 = fmaxf(mx0, __shfl_xor_sync(0xffffffffu, mx0, 1));
        mx0 = fmaxf(mx0, __shfl_xor_sync(0xffffffffu, mx0, 2));
        mx1 = fmaxf(mx1, __shfl_xor_sync(0xffffffffu, mx1, 1));
        mx1 = fmaxf(mx1, __shfl_xor_sync(0xffffffffu, mx1, 2));
        const float mn0 = fmaxf(m0, mx0);
        const float mn1 = fmaxf(m1, mx1);
        const float sf0 = __expf(m0 - mn0);
        const float sf1 = __expf(m1 - mn1);
        m0 = mn0; m1 = mn1;

#pragma unroll
        for (int dn = 0; dn < 8; dn++) {
            acc_o[dn][0] *= sf0; acc_o[dn][1] *= sf0;
            acc_o[dn][2] *= sf1; acc_o[dn][3] *= sf1;
        }

        // P = exp(S - m): pack directly into PV A-fragments
        uint32_t pf[4][4];
        float rs0 = 0.f, rs1 = 0.f;
#pragma unroll
        for (int kb = 0; kb < 4; kb++) {
#pragma unroll
            for (int half = 0; half < 2; half++) {
                const int ni = 2 * kb + half;
                float p0 = __expf(acc_s[ni][0] - mn0);
                float p1 = __expf(acc_s[ni][1] - mn0);
                float p2 = __expf(acc_s[ni][2] - mn1);
                float p3 = __expf(acc_s[ni][3] - mn1);
                rs0 += p0 + p1;
                rs1 += p2 + p3;
                __half2 w0 = __floats2half2_rn(p0, p1);
                __half2 w1 = __floats2half2_rn(p2, p3);
                pf[kb][half * 2 + 0] = *(uint32_t*)&w0;
                pf[kb][half * 2 + 1] = *(uint32_t*)&w1;
            }
        }
        rs0 += __shfl_xor_sync(0xffffffffu, rs0, 1);
        rs0 += __shfl_xor_sync(0xffffffffu, rs0, 2);
        rs1 += __shfl_xor_sync(0xffffffffu, rs1, 1);
        rs1 += __shfl_xor_sync(0xffffffffu, rs1, 2);
        l0 = l0 * sf0 + rs0;
        l1 = l1 * sf1 + rs1;

        // O += P V
#pragma unroll
        for (int kb = 0; kb < 4; kb++) {
            const uint32_t ko = (uint32_t)(kb * 8) * 4u;
#pragma unroll
            for (int p = 0; p < 4; p++) {
                uint32_t bf[4];
                LDSM4(bf[0], bf[1], bf[2], bf[3], vf_base + ko + (uint32_t)(p * 16 * 36) * 4u);
                mma_f16(acc_o[2*p],     pf[kb], bf);
                mma_f16(acc_o[2*p + 1], pf[kb], bf + 2);
            }
        }
        __syncthreads();
    }

    // Epilogue: normalize, store fp16 (feeds O-proj mma)
    const float i0 = 1.f / l0;
    const float i1 = 1.f / l1;
    const int row0 = b * SEQ + qb * 64 + qr;
#pragma unroll
    for (int dn = 0; dn < 8; dn++) {
        const int cp = h * (HDIM / 2) + dn * 4 + t;
        __half2 h0 = __floats2half2_rn(acc_o[dn][0] * i0, acc_o[dn][1] * i0);
        __half2 h1 = __floats2half2_rn(acc_o[dn][2] * i1, acc_o[dn][3] * i1);
        Oh[(size_t)row0 * (HIDDEN / 2) + cp] = *(uint32_t*)&h0;
        Oh[(size_t)(row0 + 8) * (HIDDEN / 2) + cp] = *(uint32_t*)&h1;
    }
}

// ---------------------------------------------------------------------------
extern "C" void kernel_launch(void* const* d_in, const int* in_sizes, int n_in,
                              void* d_out, int out_size)
{
    const float* x  = (const float*)d_in[0];
    const float* wq = (const float*)d_in[1];
    const float* bq = (const float*)d_in[2];
    const float* wk = (const float*)d_in[3];
    const float* bk = (const float*)d_in[4];
    const float* wv = (const float*)d_in[5];
    const float* bv = (const float*)d_in[6];
    const float* wo = (const float*)d_in[7];
    const float* bo = (const float*)d_in[8];
    float* out = (float*)d_out;

    __half *xh, *wqkvh, *woh, *qh, *kh, *vt, *oh;
    cudaGetSymbolAddress((void**)&xh, g_xh);
    cudaGetSymbolAddress((void**)&wqkvh, g_wqkvh);
    cudaGetSymbolAddress((void**)&woh, g_woh);
    cudaGetSymbolAddress((void**)&qh, g_qh);
    cudaGetSymbolAddress((void**)&kh, g_kh);
    cudaGetSymbolAddress((void**)&vt, g_vt);
    cudaGetSymbolAddress((void**)&oh, g_oh);

    cudaFuncSetAttribute(gemm_qkv,   cudaFuncAttributeMaxDynamicSharedMemorySize, GSM_BYTES);
    cudaFuncSetAttribute(gemm_oproj, cudaFuncAttributeMaxDynamicSharedMemorySize, GSM_BYTES);
    cudaFuncSetAttribute(attn_mma,   cudaFuncAttributeMaxDynamicSharedMemorySize, ASM_BYTES);

    cvt_all<<<(TOT4 + 255) / 256, 256>>>(
        (const float4*)x, (const float4*)wq, (const float4*)wk,
        (const float4*)wv, (const float4*)wo,
        (uint2*)xh, (uint2*)wqkvh, (uint2*)woh);

    gemm_qkv<<<dim3(NQKV / 128, MROWS / 128), 256, GSM_BYTES>>>(
        (const uint32_t*)xh, (const uint32_t*)wqkvh, bq, bk, bv,
        (uint32_t*)qh, (uint32_t*)kh, vt);

    attn_mma<<<dim3(SEQ / 64, NKV, BATCH), 512, ASM_BYTES>>>(
        (const uint32_t*)qh, (const uint32_t*)kh, (const uint32_t*)vt, (uint32_t*)oh);

    gemm_oproj<<<dim3(HIDDEN / 128, MROWS / 128), 256, GSM_BYTES>>>(
        (const uint32_t*)oh, (const uint32_t*)woh, bo, out);
}

// round 16
// speedup vs baseline: 1.1515x; 1.1250x over previous
#include <cuda_runtime.h>
#include <cuda_fp16.h>
#include <cstdint>

// Problem constants
#define BATCH 2
#define SEQ 2048
#define HIDDEN 2048
#define NHEADS 32
#define NKV 8
#define HDIM 64
#define KVDIM 512
#define MROWS (BATCH * SEQ)        // 4096
#define NQKV (HIDDEN + 2 * KVDIM)  // 3072

// Scratch (allocation-free rule: __device__ globals), all fp16
__device__ __align__(16) __half g_xh[MROWS * HIDDEN];
__device__ __align__(16) __half g_wqkvh[NQKV * HIDDEN];
__device__ __align__(16) __half g_woh[HIDDEN * HIDDEN];
__device__ __align__(16) __half g_qh[MROWS * HIDDEN];
__device__ __align__(16) __half g_kh[MROWS * KVDIM];
__device__ __align__(16) __half g_vt[BATCH * NKV * HDIM * SEQ];  // [b,kvh,d][s]
__device__ __align__(16) __half g_oh[MROWS * HIDDEN];

__device__ __forceinline__ void mma_f16(float* d, const uint32_t* a, const uint32_t* b) {
    asm volatile(
        "mma.sync.aligned.m16n8k16.row.col.f32.f16.f16.f32 "
        "{%0,%1,%2,%3}, {%4,%5,%6,%7}, {%8,%9}, {%0,%1,%2,%3};"
        : "+f"(d[0]), "+f"(d[1]), "+f"(d[2]), "+f"(d[3])
        : "r"(a[0]), "r"(a[1]), "r"(a[2]), "r"(a[3]), "r"(b[0]), "r"(b[1]));
}

#define LDSM4(r0, r1, r2, r3, addr) \
    asm volatile("ldmatrix.sync.aligned.m8n8.x4.shared.b16 {%0,%1,%2,%3}, [%4];" \
        : "=r"(r0), "=r"(r1), "=r"(r2), "=r"(r3) : "r"(addr))

__device__ __forceinline__ uint32_t smem_u32(const void* p) {
    uint32_t a;
    asm("{ .reg .u64 t; cvta.to.shared.u64 t, %1; cvt.u32.u64 %0, t; }" : "=r"(a) : "l"(p));
    return a;
}

__device__ __forceinline__ void cpasync16(uint32_t dst, const void* src) {
    asm volatile("cp.async.ca.shared.global [%0], [%1], 16;" :: "r"(dst), "l"(src));
}

// ---------------------------------------------------------------------------
// Fused fp32 -> fp16 conversion for all five tensors (single launch)
// ---------------------------------------------------------------------------
#define X4C (MROWS * HIDDEN / 4)
#define Q4C (HIDDEN * HIDDEN / 4)
#define K4C (KVDIM * HIDDEN / 4)
#define TOT4 (X4C + Q4C + 2 * K4C + Q4C)

__global__ void cvt_all(
    const float4* __restrict__ x,  const float4* __restrict__ wq,
    const float4* __restrict__ wk, const float4* __restrict__ wv,
    const float4* __restrict__ wo,
    uint2* __restrict__ xh, uint2* __restrict__ wqkvh, uint2* __restrict__ woh)
{
    int i = blockIdx.x * blockDim.x + threadIdx.x;
    if (i >= TOT4) return;
    float4 v;
    uint2* out;
    if (i < X4C)                      { v = x[i];                      out = xh + i; }
    else if (i < X4C + Q4C)           { int j = i - X4C;               v = wq[j]; out = wqkvh + j; }
    else if (i < X4C + Q4C + K4C)     { int j = i - X4C - Q4C;         v = wk[j]; out = wqkvh + Q4C + j; }
    else if (i < X4C + Q4C + 2 * K4C) { int j = i - X4C - Q4C - K4C;   v = wv[j]; out = wqkvh + Q4C + K4C + j; }
    else                              { int j = i - X4C - Q4C - 2*K4C; v = wo[j]; out = woh + j; }
    __half2 h0 = __floats2half2_rn(v.x, v.y);
    __half2 h1 = __floats2half2_rn(v.z, v.w);
    uint2 o;
    o.x = *(uint32_t*)&h0;
    o.y = *(uint32_t*)&h1;
    *out = o;
}

// ---------------------------------------------------------------------------
// fp16 GEMM core: C[M,N] = A[M,K] @ W[N,K]^T, fp32 accum, ldmatrix fragments.
// CTA tile 128x256 (cuts SMEM-fill ops 25% vs 128x128 -> the measured limiter),
// BK=64 (32 uint32/row, stride 36), 512 threads = 16 warps (2 wm x 8 wn),
// warp tile 64x32 (validated mapping). 3-stage cp.async, 166 KB smem, 1 CTA/SM.
// ---------------------------------------------------------------------------
#define GTS 36
#define GA_W (128 * GTS)                      // A words per stage (4608)
#define GSTAGE_W ((128 + 256) * GTS)          // words per stage (13824)
#define GSM_BYTES (3 * GSTAGE_W * 4)          // 165888

struct GemmCore {
    uint32_t sbase;
    const uint32_t* A;
    const uint32_t* W;
    int K2;
    int bm, bn, tid;

    __device__ __forceinline__ void issue(int kt, int s) {
        const int k0u = kt << 5;              // 32 uint32 per BK=64 tile
        const uint32_t so = (uint32_t)(s * GSTAGE_W);
        // A: 128 rows x 8 uint4 = 1024 loads (2/thread)
#pragma unroll
        for (int j = 0; j < 2; j++) {
            int idx = j * 512 + tid;
            int r = idx >> 3, c4 = (idx & 7) * 4;
            uint32_t off = (so + (uint32_t)(r * GTS + c4)) * 4u;
            cpasync16(sbase + off, A + (size_t)(bm + r) * K2 + k0u + c4);
        }
        // B: 256 rows x 8 uint4 = 2048 loads (4/thread)
#pragma unroll
        for (int j = 0; j < 4; j++) {
            int idx = j * 512 + tid;
            int r = idx >> 3, c4 = (idx & 7) * 4;
            uint32_t off = (so + (uint32_t)(GA_W + r * GTS + c4)) * 4u;
            cpasync16(sbase + off, W + (size_t)(bn + r) * K2 + k0u + c4);
        }
        asm volatile("cp.async.commit_group;" ::: "memory");
    }

    __device__ __forceinline__ void run(float acc[4][4][4], int wm, int wn, int lane) {
        const uint32_t a_base = sbase +
            (uint32_t)(((wm + (lane & 7) + ((lane >> 3) & 1) * 8) * GTS + ((lane >> 4) & 1) * 4) * 4);
        const uint32_t b_base = sbase + (uint32_t)GA_W * 4u +
            (uint32_t)(((wn + (lane & 7) + ((lane >> 4) & 1) * 8) * GTS + ((lane >> 3) & 1) * 4) * 4);

        const int NT = K2 >> 5;
        issue(0, 0);
        issue(1, 1);
        for (int kt = 0; kt < NT; kt++) {
            if (kt < NT - 1) {
                asm volatile("cp.async.wait_group %0;" :: "n"(1) : "memory");
            } else {
                asm volatile("cp.async.wait_group %0;" :: "n"(0) : "memory");
            }
            __syncthreads();
            if (kt + 2 < NT) issue(kt + 2, (kt + 2) % 3);
            const uint32_t so = (uint32_t)((kt % 3) * GSTAGE_W) * 4u;
#pragma unroll
            for (int kk = 0; kk < 4; kk++) {
                const uint32_t ko = (uint32_t)(kk * 8) * 4u;
                uint32_t af[4][4];
#pragma unroll
                for (int mi = 0; mi < 4; mi++)
                    LDSM4(af[mi][0], af[mi][1], af[mi][2], af[mi][3],
                          a_base + so + ko + (uint32_t)(mi * 16 * GTS) * 4u);
                uint32_t bf[4][2];
#pragma unroll
                for (int p = 0; p < 2; p++)
                    LDSM4(bf[2*p][0], bf[2*p][1], bf[2*p+1][0], bf[2*p+1][1],
                          b_base + so + ko + (uint32_t)(p * 16 * GTS) * 4u);
#pragma unroll
                for (int mi = 0; mi < 4; mi++)
#pragma unroll
                    for (int ni = 0; ni < 4; ni++)
                        mma_f16(acc[mi][ni], af[mi], bf[ni]);
            }
        }
    }
};

// Fused QKV projection; q/k written fp16 row-major, v written fp16 TRANSPOSED.
// bn granularity 256; section boundaries 2048/2560/3072 are 256-aligned.
__global__ __launch_bounds__(512, 1) void gemm_qkv(
    const uint32_t* __restrict__ A, const uint32_t* __restrict__ Wc,
    const float* __restrict__ bq, const float* __restrict__ bk, const float* __restrict__ bv,
    uint32_t* __restrict__ q, uint32_t* __restrict__ k, __half* __restrict__ vt)
{
    extern __shared__ uint32_t sh[];
    const int tid = threadIdx.x;
    const int wid = tid >> 5;
    const int lane = tid & 31;
    const int g = lane >> 2, t = lane & 3;
    const int wm = (wid & 1) * 64, wn = (wid >> 1) * 32;
    const int bm = blockIdx.y * 128, bn = blockIdx.x * 256;

    GemmCore core{smem_u32(sh), A, Wc, HIDDEN / 2, bm, bn, tid};
    float acc[4][4][4] = {};
    core.run(acc, wm, wn, lane);

    if (bn < HIDDEN) {
        const float* bias = bq;
#pragma unroll
        for (int mi = 0; mi < 4; mi++)
#pragma unroll
            for (int ni = 0; ni < 4; ni++) {
                const int col = bn + wn + ni * 8 + 2 * t;
                const float bx = __ldg(bias + col);
                const float by = __ldg(bias + col + 1);
                const int rr0 = bm + wm + mi * 16 + g;
                __half2 h0 = __floats2half2_rn(acc[mi][ni][0] + bx, acc[mi][ni][1] + by);
                __half2 h1 = __floats2half2_rn(acc[mi][ni][2] + bx, acc[mi][ni][3] + by);
                q[(size_t)rr0 * (HIDDEN / 2) + (col >> 1)] = *(uint32_t*)&h0;
                q[(size_t)(rr0 + 8) * (HIDDEN / 2) + (col >> 1)] = *(uint32_t*)&h1;
            }
    } else if (bn < HIDDEN + KVDIM) {
        const float* bias = bk;
        const int cb = bn - HIDDEN;
#pragma unroll
        for (int mi = 0; mi < 4; mi++)
#pragma unroll
            for (int ni = 0; ni < 4; ni++) {
                const int col = cb + wn + ni * 8 + 2 * t;
                const float bx = __ldg(bias + col);
                const float by = __ldg(bias + col + 1);
                const int rr0 = bm + wm + mi * 16 + g;
                __half2 h0 = __floats2half2_rn(acc[mi][ni][0] + bx, acc[mi][ni][1] + by);
                __half2 h1 = __floats2half2_rn(acc[mi][ni][2] + bx, acc[mi][ni][3] + by);
                k[(size_t)rr0 * (KVDIM / 2) + (col >> 1)] = *(uint32_t*)&h0;
                k[(size_t)(rr0 + 8) * (KVDIM / 2) + (col >> 1)] = *(uint32_t*)&h1;
            }
    } else {
        const float* bias = bv;
        const int cb = bn - HIDDEN - KVDIM;
#pragma unroll
        for (int mi = 0; mi < 4; mi++)
#pragma unroll
            for (int ni = 0; ni < 4; ni++) {
                const int col = cb + wn + ni * 8 + 2 * t;   // d index (even)
                const float bx = __ldg(bias + col);
                const float by = __ldg(bias + col + 1);
#pragma unroll
                for (int rr = 0; rr < 2; rr++) {
                    const int row = bm + wm + mi * 16 + g + rr * 8;
                    const int bb = row >> 11;
                    const int s  = row & 2047;
                    const float v0 = acc[mi][ni][rr * 2 + 0] + bx;
                    const float v1 = acc[mi][ni][rr * 2 + 1] + by;
                    const size_t base = ((size_t)(bb * NKV + (col >> 6)) * HDIM);
                    vt[(base + (col & 63)) * SEQ + s]     = __float2half_rn(v0);
                    vt[(base + (col & 63) + 1) * SEQ + s] = __float2half_rn(v1);
                }
            }
    }
}

// O-projection: fp16 inputs, fp32 output + bias.
__global__ __launch_bounds__(512, 1) void gemm_oproj(
    const uint32_t* __restrict__ A, const uint32_t* __restrict__ W,
    const float* __restrict__ bias, float* __restrict__ C)
{
    extern __shared__ uint32_t sh[];
    const int tid = threadIdx.x;
    const int wid = tid >> 5;
    const int lane = tid & 31;
    const int g = lane >> 2, t = lane & 3;
    const int wm = (wid & 1) * 64, wn = (wid >> 1) * 32;
    const int bm = blockIdx.y * 128, bn = blockIdx.x * 256;

    GemmCore core{smem_u32(sh), A, W, HIDDEN / 2, bm, bn, tid};
    float acc[4][4][4] = {};
    core.run(acc, wm, wn, lane);

#pragma unroll
    for (int mi = 0; mi < 4; mi++)
#pragma unroll
        for (int ni = 0; ni < 4; ni++) {
            const int col = bn + wn + ni * 8 + 2 * t;
            const float bx = __ldg(bias + col);
            const float by = __ldg(bias + col + 1);
            const int rr0 = bm + wm + mi * 16 + g;
            float2 v0, v1;
            v0.x = acc[mi][ni][0] + bx; v0.y = acc[mi][ni][1] + by;
            v1.x = acc[mi][ni][2] + bx; v1.y = acc[mi][ni][3] + by;
            *(float2*)(C + (size_t)rr0 * HIDDEN + col) = v0;
            *(float2*)(C + (size_t)(rr0 + 8) * HIDDEN + col) = v1;
        }
}

// ---------------------------------------------------------------------------
// fp16 flash attention: EXACT R11/R12 version (proven best).
// Register-resident P, ldmatrix K/V fragments, double-buffered cp.async.
// SMEM (uint32): Qs 128x36 | Ks 2x64x36 | Vt 2x64x36 = 55296 B -> 2 CTAs/SM.
// ---------------------------------------------------------------------------
#define ASM_BYTES ((128 * 36 + 2 * 64 * 36 + 2 * 64 * 36) * 4)

__global__ __launch_bounds__(256, 2) void attn_mma(
    const uint32_t* __restrict__ Qh, const uint32_t* __restrict__ Kh,
    const uint32_t* __restrict__ Vth, uint32_t* __restrict__ Oh)
{
    extern __shared__ uint32_t sm32[];
    uint32_t* Qs = sm32;                     // [128][36] (staging only)
    const uint32_t sbase = smem_u32(sm32);
    const uint32_t ks_off = (uint32_t)(128 * 36) * 4u;
    const uint32_t vt_off = ks_off + 2u * 64u * 36u * 4u;

    const int tid = threadIdx.x;
    const int wid = tid >> 5;
    const int lane = tid & 31;
    const int g = lane >> 2;
    const int t = lane & 3;
    const int qb = blockIdx.x;
    const int h  = blockIdx.y;
    const int b  = blockIdx.z;
    const int kvh = h >> 2;

    const uint32_t* Kbase  = Kh + (size_t)(b * SEQ) * (KVDIM / 2) + kvh * (HDIM / 2);
    const uint32_t* Vtbase = Vth + (size_t)((b * NKV + kvh) * HDIM) * (SEQ / 2);

    const uint32_t bl_off =
        (uint32_t)((((lane & 7) + ((lane >> 4) & 1) * 8) * 36 + ((lane >> 3) & 1) * 4) * 4);

    auto issue = [&](int jb, int s) {
#pragma unroll
        for (int j = 0; j < 2; j++) {
            int idx = j * 256 + tid;
            int r = idx >> 3, c4 = (idx & 7) * 4;
            uint32_t so = (uint32_t)(s * 64 * 36 + r * 36 + c4) * 4u;
            cpasync16(sbase + ks_off + so, Kbase + (size_t)(jb * 64 + r) * (KVDIM / 2) + c4);
            cpasync16(sbase + vt_off + so, Vtbase + (size_t)r * (SEQ / 2) + jb * 32 + c4);
        }
        asm volatile("cp.async.commit_group;" ::: "memory");
    };

    issue(0, 0);

    // Stage Q tile (coalesced), scale by 1/8
    {
        const __half2 sc = __float2half2_rn(0.125f);
        const uint32_t* src = Qh + (size_t)(b * SEQ + qb * 128) * (HIDDEN / 2) + h * (HDIM / 2);
#pragma unroll
        for (int j = 0; j < 4; j++) {
            int idx = j * 256 + tid;
            int r = idx >> 3, c = (idx & 7) * 4;
            uint4 v = *(const uint4*)(src + (size_t)r * (HIDDEN / 2) + c);
            __half2* hp = (__half2*)&v;
            hp[0] = __hmul2(hp[0], sc); hp[1] = __hmul2(hp[1], sc);
            hp[2] = __hmul2(hp[2], sc); hp[3] = __hmul2(hp[3], sc);
            uint32_t* dst = &Qs[r * 36 + c];
            dst[0] = v.x; dst[1] = v.y; dst[2] = v.z; dst[3] = v.w;
        }
    }
    __syncthreads();

    const int qr = wid * 16 + g;
    uint32_t qf[4][4];
#pragma unroll
    for (int kk = 0; kk < 4; kk++) {
        const int kc = kk * 8 + t;
        qf[kk][0] = Qs[qr * 36 + kc];
        qf[kk][1] = Qs[(qr + 8) * 36 + kc];
        qf[kk][2] = Qs[qr * 36 + kc + 4];
        qf[kk][3] = Qs[(qr + 8) * 36 + kc + 4];
    }

    float acc_o[8][4] = {};
    float m0 = -1e30f, m1 = -1e30f, l0 = 0.f, l1 = 0.f;

    for (int jb = 0; jb < SEQ / 64; jb++) {
        const int s = jb & 1;
        if (jb + 1 < SEQ / 64) {
            issue(jb + 1, s ^ 1);
            asm volatile("cp.async.wait_group %0;" :: "n"(1) : "memory");
        } else {
            asm volatile("cp.async.wait_group %0;" :: "n"(0) : "memory");
        }
        __syncthreads();

        const uint32_t kf_base = sbase + ks_off + (uint32_t)(s * 64 * 36) * 4u + bl_off;
        const uint32_t vf_base = sbase + vt_off + (uint32_t)(s * 64 * 36) * 4u + bl_off;

        // S = Q K^T
        float acc_s[8][4] = {};
#pragma unroll
        for (int kk = 0; kk < 4; kk++) {
            const uint32_t ko = (uint32_t)(kk * 8) * 4u;
#pragma unroll
            for (int p = 0; p < 4; p++) {
                uint32_t bf[4];
                LDSM4(bf[0], bf[1], bf[2], bf[3], kf_base + ko + (uint32_t)(p * 16 * 36) * 4u);
                mma_f16(acc_s[2*p],     qf[kk], bf);
                mma_f16(acc_s[2*p + 1], qf[kk], bf + 2);
            }
        }

        // Fragment online softmax
        float mx0 = -1e30f, mx1 = -1e30f;
#pragma unroll
        for (int ni = 0; ni < 8; ni++) {
            mx0 = fmaxf(mx0, fmaxf(acc_s[ni][0], acc_s[ni][1]));
            mx1 = fmaxf(mx1, fmaxf(acc_s[ni][2], acc_s[ni][3]));
        }
        mx0 = fmaxf(mx0, __shfl_xor_sync(0xffffffffu, mx0, 1));
        mx0 = fmaxf(mx0, __shfl_xor_sync(0xffffffffu, mx0, 2));
        mx1 = fmaxf(mx1, __shfl_xor_sync(0xffffffffu, mx1, 1));
        mx1 = fmaxf(mx1, __shfl_xor_sync(0xffffffffu, mx1, 2));
        const float mn0 = fmaxf(m0, mx0);
        const float mn1 = fmaxf(m1, mx1);
        const float sf0 = __expf(m0 - mn0);
        const float sf1 = __expf(m1 - mn1);
        m0 = mn0; m1 = mn1;

#pragma unroll
        for (int dn = 0; dn < 8; dn++) {
            acc_o[dn][0] *= sf0; acc_o[dn][1] *= sf0;
            acc_o[dn][2] *= sf1; acc_o[dn][3] *= sf1;
        }

        // P = exp(S - m): pack directly into PV A-fragments
        uint32_t pf[4][4];
        float rs0 = 0.f, rs1 = 0.f;
#pragma unroll
        for (int kb = 0; kb < 4; kb++) {
#pragma unroll
            for (int half = 0; half < 2; half++) {
                const int ni = 2 * kb + half;
                float p0 = __expf(acc_s[ni][0] - mn0);
                float p1 = __expf(acc_s[ni][1] - mn0);
                float p2 = __expf(acc_s[ni][2] - mn1);
                float p3 = __expf(acc_s[ni][3] - mn1);
                rs0 += p0 + p1;
                rs1 += p2 + p3;
                __half2 w0 = __floats2half2_rn(p0, p1);
                __half2 w1 = __floats2half2_rn(p2, p3);
                pf[kb][half * 2 + 0] = *(uint32_t*)&w0;
                pf[kb][half * 2 + 1] = *(uint32_t*)&w1;
            }
        }
        rs0 += __shfl_xor_sync(0xffffffffu, rs0, 1);
        rs0 += __shfl_xor_sync(0xffffffffu, rs0, 2);
        rs1 += __shfl_xor_sync(0xffffffffu, rs1, 1);
        rs1 += __shfl_xor_sync(0xffffffffu, rs1, 2);
        l0 = l0 * sf0 + rs0;
        l1 = l1 * sf1 + rs1;

        // O += P V
#pragma unroll
        for (int kb = 0; kb < 4; kb++) {
            const uint32_t ko = (uint32_t)(kb * 8) * 4u;
#pragma unroll
            for (int p = 0; p < 4; p++) {
                uint32_t bf[4];
                LDSM4(bf[0], bf[1], bf[2], bf[3], vf_base + ko + (uint32_t)(p * 16 * 36) * 4u);
                mma_f16(acc_o[2*p],     pf[kb], bf);
                mma_f16(acc_o[2*p + 1], pf[kb], bf + 2);
            }
        }
        __syncthreads();
    }

    // Epilogue: normalize, store fp16 (feeds O-proj mma)
    const float i0 = 1.f / l0;
    const float i1 = 1.f / l1;
    const int row0 = b * SEQ + qb * 128 + qr;
#pragma unroll
    for (int dn = 0; dn < 8; dn++) {
        const int cp = h * (HDIM / 2) + dn * 4 + t;
        __half2 h0 = __floats2half2_rn(acc_o[dn][0] * i0, acc_o[dn][1] * i0);
        __half2 h1 = __floats2half2_rn(acc_o[dn][2] * i1, acc_o[dn][3] * i1);
        Oh[(size_t)row0 * (HIDDEN / 2) + cp] = *(uint32_t*)&h0;
        Oh[(size_t)(row0 + 8) * (HIDDEN / 2) + cp] = *(uint32_t*)&h1;
    }
}

// ---------------------------------------------------------------------------
extern "C" void kernel_launch(void* const* d_in, const int* in_sizes, int n_in,
                              void* d_out, int out_size)
{
    const float* x  = (const float*)d_in[0];
    const float* wq = (const float*)d_in[1];
    const float* bq = (const float*)d_in[2];
    const float* wk = (const float*)d_in[3];
    const float* bk = (const float*)d_in[4];
    const float* wv = (const float*)d_in[5];
    const float* bv = (const float*)d_in[6];
    const float* wo = (const float*)d_in[7];
    const float* bo = (const float*)d_in[8];
    float* out = (float*)d_out;

    __half *xh, *wqkvh, *woh, *qh, *kh, *vt, *oh;
    cudaGetSymbolAddress((void**)&xh, g_xh);
    cudaGetSymbolAddress((void**)&wqkvh, g_wqkvh);
    cudaGetSymbolAddress((void**)&woh, g_woh);
    cudaGetSymbolAddress((void**)&qh, g_qh);
    cudaGetSymbolAddress((void**)&kh, g_kh);
    cudaGetSymbolAddress((void**)&vt, g_vt);
    cudaGetSymbolAddress((void**)&oh, g_oh);

    cudaFuncSetAttribute(gemm_qkv,   cudaFuncAttributeMaxDynamicSharedMemorySize, GSM_BYTES);
    cudaFuncSetAttribute(gemm_oproj, cudaFuncAttributeMaxDynamicSharedMemorySize, GSM_BYTES);
    cudaFuncSetAttribute(attn_mma,   cudaFuncAttributeMaxDynamicSharedMemorySize, ASM_BYTES);

    cvt_all<<<(TOT4 + 255) / 256, 256>>>(
        (const float4*)x, (const float4*)wq, (const float4*)wk,
        (const float4*)wv, (const float4*)wo,
        (uint2*)xh, (uint2*)wqkvh, (uint2*)woh);

    gemm_qkv<<<dim3(NQKV / 256, MROWS / 128), 512, GSM_BYTES>>>(
        (const uint32_t*)xh, (const uint32_t*)wqkvh, bq, bk, bv,
        (uint32_t*)qh, (uint32_t*)kh, vt);

    attn_mma<<<dim3(SEQ / 128, NHEADS, BATCH), 256, ASM_BYTES>>>(
        (const uint32_t*)qh, (const uint32_t*)kh, (const uint32_t*)vt, (uint32_t*)oh);

    gemm_oproj<<<dim3(HIDDEN / 256, MROWS / 128), 512, GSM_BYTES>>>(
        (const uint32_t*)oh, (const uint32_t*)woh, bo, out);
}

// round 17
// speedup vs baseline: 1.1515x; 1.0001x over previous
#include <cuda_runtime.h>
#include <cuda_fp16.h>
#include <cstdint>

// Problem constants
#define BATCH 2
#define SEQ 2048
#define HIDDEN 2048
#define NHEADS 32
#define NKV 8
#define HDIM 64
#define KVDIM 512
#define MROWS (BATCH * SEQ)        // 4096
#define NQKV (HIDDEN + 2 * KVDIM)  // 3072

// Scratch (allocation-free rule: __device__ globals), all fp16
__device__ __align__(16) __half g_xh[MROWS * HIDDEN];
__device__ __align__(16) __half g_wqkvh[NQKV * HIDDEN];
__device__ __align__(16) __half g_woh[HIDDEN * HIDDEN];
__device__ __align__(16) __half g_qh[MROWS * HIDDEN];
__device__ __align__(16) __half g_kh[MROWS * KVDIM];
__device__ __align__(16) __half g_vt[BATCH * NKV * HDIM * SEQ];  // [b,kvh,d][s]
__device__ __align__(16) __half g_oh[MROWS * HIDDEN];

__device__ __forceinline__ void mma_f16(float* d, const uint32_t* a, const uint32_t* b) {
    asm volatile(
        "mma.sync.aligned.m16n8k16.row.col.f32.f16.f16.f32 "
        "{%0,%1,%2,%3}, {%4,%5,%6,%7}, {%8,%9}, {%0,%1,%2,%3};"
        : "+f"(d[0]), "+f"(d[1]), "+f"(d[2]), "+f"(d[3])
        : "r"(a[0]), "r"(a[1]), "r"(a[2]), "r"(a[3]), "r"(b[0]), "r"(b[1]));
}

#define LDSM4(r0, r1, r2, r3, addr) \
    asm volatile("ldmatrix.sync.aligned.m8n8.x4.shared.b16 {%0,%1,%2,%3}, [%4];" \
        : "=r"(r0), "=r"(r1), "=r"(r2), "=r"(r3) : "r"(addr))

__device__ __forceinline__ uint32_t smem_u32(const void* p) {
    uint32_t a;
    asm("{ .reg .u64 t; cvta.to.shared.u64 t, %1; cvt.u32.u64 %0, t; }" : "=r"(a) : "l"(p));
    return a;
}

__device__ __forceinline__ void cpasync16(uint32_t dst, const void* src) {
    asm volatile("cp.async.ca.shared.global [%0], [%1], 16;" :: "r"(dst), "l"(src));
}

// ---------------------------------------------------------------------------
// Fused fp32 -> fp16 conversion for all five tensors (single launch)
// ---------------------------------------------------------------------------
#define X4C (MROWS * HIDDEN / 4)
#define Q4C (HIDDEN * HIDDEN / 4)
#define K4C (KVDIM * HIDDEN / 4)
#define TOT4 (X4C + Q4C + 2 * K4C + Q4C)

__global__ void cvt_all(
    const float4* __restrict__ x,  const float4* __restrict__ wq,
    const float4* __restrict__ wk, const float4* __restrict__ wv,
    const float4* __restrict__ wo,
    uint2* __restrict__ xh, uint2* __restrict__ wqkvh, uint2* __restrict__ woh)
{
    int i = blockIdx.x * blockDim.x + threadIdx.x;
    if (i >= TOT4) return;
    float4 v;
    uint2* out;
    if (i < X4C)                      { v = x[i];                      out = xh + i; }
    else if (i < X4C + Q4C)           { int j = i - X4C;               v = wq[j]; out = wqkvh + j; }
    else if (i < X4C + Q4C + K4C)     { int j = i - X4C - Q4C;         v = wk[j]; out = wqkvh + Q4C + j; }
    else if (i < X4C + Q4C + 2 * K4C) { int j = i - X4C - Q4C - K4C;   v = wv[j]; out = wqkvh + Q4C + K4C + j; }
    else                              { int j = i - X4C - Q4C - 2*K4C; v = wo[j]; out = woh + j; }
    __half2 h0 = __floats2half2_rn(v.x, v.y);
    __half2 h1 = __floats2half2_rn(v.z, v.w);
    uint2 o;
    o.x = *(uint32_t*)&h0;
    o.y = *(uint32_t*)&h1;
    *out = o;
}

// ---------------------------------------------------------------------------
// fp16 GEMM core (R16 proven): CTA 128x256, BK=64 (stride 36), 512 threads
// = 16 warps (2 wm x 8 wn), warp tile 64x32. 3-stage cp.async, 166 KB smem.
// ---------------------------------------------------------------------------
#define GTS 36
#define GA_W (128 * GTS)
#define GSTAGE_W ((128 + 256) * GTS)
#define GSM_BYTES (3 * GSTAGE_W * 4)          // 165888

struct GemmCore {
    uint32_t sbase;
    const uint32_t* A;
    const uint32_t* W;
    int K2;
    int bm, bn, tid;

    __device__ __forceinline__ void issue(int kt, int s) {
        const int k0u = kt << 5;
        const uint32_t so = (uint32_t)(s * GSTAGE_W);
#pragma unroll
        for (int j = 0; j < 2; j++) {
            int idx = j * 512 + tid;
            int r = idx >> 3, c4 = (idx & 7) * 4;
            uint32_t off = (so + (uint32_t)(r * GTS + c4)) * 4u;
            cpasync16(sbase + off, A + (size_t)(bm + r) * K2 + k0u + c4);
        }
#pragma unroll
        for (int j = 0; j < 4; j++) {
            int idx = j * 512 + tid;
            int r = idx >> 3, c4 = (idx & 7) * 4;
            uint32_t off = (so + (uint32_t)(GA_W + r * GTS + c4)) * 4u;
            cpasync16(sbase + off, W + (size_t)(bn + r) * K2 + k0u + c4);
        }
        asm volatile("cp.async.commit_group;" ::: "memory");
    }

    __device__ __forceinline__ void run(float acc[4][4][4], int wm, int wn, int lane) {
        const uint32_t a_base = sbase +
            (uint32_t)(((wm + (lane & 7) + ((lane >> 3) & 1) * 8) * GTS + ((lane >> 4) & 1) * 4) * 4);
        const uint32_t b_base = sbase + (uint32_t)GA_W * 4u +
            (uint32_t)(((wn + (lane & 7) + ((lane >> 4) & 1) * 8) * GTS + ((lane >> 3) & 1) * 4) * 4);

        const int NT = K2 >> 5;
        issue(0, 0);
        issue(1, 1);
        for (int kt = 0; kt < NT; kt++) {
            if (kt < NT - 1) {
                asm volatile("cp.async.wait_group %0;" :: "n"(1) : "memory");
            } else {
                asm volatile("cp.async.wait_group %0;" :: "n"(0) : "memory");
            }
            __syncthreads();
            if (kt + 2 < NT) issue(kt + 2, (kt + 2) % 3);
            const uint32_t so = (uint32_t)((kt % 3) * GSTAGE_W) * 4u;
#pragma unroll
            for (int kk = 0; kk < 4; kk++) {
                const uint32_t ko = (uint32_t)(kk * 8) * 4u;
                uint32_t af[4][4];
#pragma unroll
                for (int mi = 0; mi < 4; mi++)
                    LDSM4(af[mi][0], af[mi][1], af[mi][2], af[mi][3],
                          a_base + so + ko + (uint32_t)(mi * 16 * GTS) * 4u);
                uint32_t bf[4][2];
#pragma unroll
                for (int p = 0; p < 2; p++)
                    LDSM4(bf[2*p][0], bf[2*p][1], bf[2*p+1][0], bf[2*p+1][1],
                          b_base + so + ko + (uint32_t)(p * 16 * GTS) * 4u);
#pragma unroll
                for (int mi = 0; mi < 4; mi++)
#pragma unroll
                    for (int ni = 0; ni < 4; ni++)
                        mma_f16(acc[mi][ni], af[mi], bf[ni]);
            }
        }
    }
};

// Fused QKV projection; q/k written fp16 row-major, v written fp16 TRANSPOSED.
__global__ __launch_bounds__(512, 1) void gemm_qkv(
    const uint32_t* __restrict__ A, const uint32_t* __restrict__ Wc,
    const float* __restrict__ bq, const float* __restrict__ bk, const float* __restrict__ bv,
    uint32_t* __restrict__ q, uint32_t* __restrict__ k, __half* __restrict__ vt)
{
    extern __shared__ uint32_t sh[];
    const int tid = threadIdx.x;
    const int wid = tid >> 5;
    const int lane = tid & 31;
    const int g = lane >> 2, t = lane & 3;
    const int wm = (wid & 1) * 64, wn = (wid >> 1) * 32;
    const int bm = blockIdx.y * 128, bn = blockIdx.x * 256;

    GemmCore core{smem_u32(sh), A, Wc, HIDDEN / 2, bm, bn, tid};
    float acc[4][4][4] = {};
    core.run(acc, wm, wn, lane);

    if (bn < HIDDEN) {
        const float* bias = bq;
#pragma unroll
        for (int mi = 0; mi < 4; mi++)
#pragma unroll
            for (int ni = 0; ni < 4; ni++) {
                const int col = bn + wn + ni * 8 + 2 * t;
                const float bx = __ldg(bias + col);
                const float by = __ldg(bias + col + 1);
                const int rr0 = bm + wm + mi * 16 + g;
                __half2 h0 = __floats2half2_rn(acc[mi][ni][0] + bx, acc[mi][ni][1] + by);
                __half2 h1 = __floats2half2_rn(acc[mi][ni][2] + bx, acc[mi][ni][3] + by);
                q[(size_t)rr0 * (HIDDEN / 2) + (col >> 1)] = *(uint32_t*)&h0;
                q[(size_t)(rr0 + 8) * (HIDDEN / 2) + (col >> 1)] = *(uint32_t*)&h1;
            }
    } else if (bn < HIDDEN + KVDIM) {
        const float* bias = bk;
        const int cb = bn - HIDDEN;
#pragma unroll
        for (int mi = 0; mi < 4; mi++)
#pragma unroll
            for (int ni = 0; ni < 4; ni++) {
                const int col = cb + wn + ni * 8 + 2 * t;
                const float bx = __ldg(bias + col);
                const float by = __ldg(bias + col + 1);
                const int rr0 = bm + wm + mi * 16 + g;
                __half2 h0 = __floats2half2_rn(acc[mi][ni][0] + bx, acc[mi][ni][1] + by);
                __half2 h1 = __floats2half2_rn(acc[mi][ni][2] + bx, acc[mi][ni][3] + by);
                k[(size_t)rr0 * (KVDIM / 2) + (col >> 1)] = *(uint32_t*)&h0;
                k[(size_t)(rr0 + 8) * (KVDIM / 2) + (col >> 1)] = *(uint32_t*)&h1;
            }
    } else {
        const float* bias = bv;
        const int cb = bn - HIDDEN - KVDIM;
#pragma unroll
        for (int mi = 0; mi < 4; mi++)
#pragma unroll
            for (int ni = 0; ni < 4; ni++) {
                const int col = cb + wn + ni * 8 + 2 * t;   // d index (even)
                const float bx = __ldg(bias + col);
                const float by = __ldg(bias + col + 1);
#pragma unroll
                for (int rr = 0; rr < 2; rr++) {
                    const int row = bm + wm + mi * 16 + g + rr * 8;
                    const int bb = row >> 11;
                    const int s  = row & 2047;
                    const float v0 = acc[mi][ni][rr * 2 + 0] + bx;
                    const float v1 = acc[mi][ni][rr * 2 + 1] + by;
                    const size_t base = ((size_t)(bb * NKV + (col >> 6)) * HDIM);
                    vt[(base + (col & 63)) * SEQ + s]     = __float2half_rn(v0);
                    vt[(base + (col & 63) + 1) * SEQ + s] = __float2half_rn(v1);
                }
            }
    }
}

// O-projection: fp16 inputs, fp32 output + bias.
__global__ __launch_bounds__(512, 1) void gemm_oproj(
    const uint32_t* __restrict__ A, const uint32_t* __restrict__ W,
    const float* __restrict__ bias, float* __restrict__ C)
{
    extern __shared__ uint32_t sh[];
    const int tid = threadIdx.x;
    const int wid = tid >> 5;
    const int lane = tid & 31;
    const int g = lane >> 2, t = lane & 3;
    const int wm = (wid & 1) * 64, wn = (wid >> 1) * 32;
    const int bm = blockIdx.y * 128, bn = blockIdx.x * 256;

    GemmCore core{smem_u32(sh), A, W, HIDDEN / 2, bm, bn, tid};
    float acc[4][4][4] = {};
    core.run(acc, wm, wn, lane);

#pragma unroll
    for (int mi = 0; mi < 4; mi++)
#pragma unroll
        for (int ni = 0; ni < 4; ni++) {
            const int col = bn + wn + ni * 8 + 2 * t;
            const float bx = __ldg(bias + col);
            const float by = __ldg(bias + col + 1);
            const int rr0 = bm + wm + mi * 16 + g;
            float2 v0, v1;
            v0.x = acc[mi][ni][0] + bx; v0.y = acc[mi][ni][1] + by;
            v1.x = acc[mi][ni][2] + bx; v1.y = acc[mi][ni][3] + by;
            *(float2*)(C + (size_t)rr0 * HIDDEN + col) = v0;
            *(float2*)(C + (size_t)(rr0 + 8) * HIDDEN + col) = v1;
        }
}

// ---------------------------------------------------------------------------
// fp16 flash attention with GQA head-PAIR sharing (K/V fill ops halved vs R11
// while keeping the proven shape: 256 threads, 8 warps, 2 CTAs/SM).
// CTA = (64-query tile, head-pair, batch). Warps: wid>>2 = head-in-pair (0/1),
// wid&3 = 16-row subtile. Heads 2j/2j+1 share kvh (group=4), so one K/V
// stream serves both. Per-warp inner loop = exact R11 (register P, ldmatrix
// K/V frags, double-buffered cp.async).
// SMEM (uint32): Qs 64x68 | Ks 2x64x36 | Vt 2x64x36 = 54272 B -> 2 CTAs/SM.
// ---------------------------------------------------------------------------
#define AQS_W (64 * 68)
#define AKV_W (64 * 36)
#define ASM_BYTES ((AQS_W + 4 * AKV_W) * 4)   // 54272

__global__ __launch_bounds__(256, 2) void attn_mma(
    const uint32_t* __restrict__ Qh, const uint32_t* __restrict__ Kh,
    const uint32_t* __restrict__ Vth, uint32_t* __restrict__ Oh)
{
    extern __shared__ uint32_t sm32[];
    uint32_t* Qs = sm32;                     // [64][68]: 2 heads x 32 u32 cols
    const uint32_t sbase = smem_u32(sm32);
    const uint32_t ks_off = (uint32_t)AQS_W * 4u;
    const uint32_t vt_off = ks_off + 2u * (uint32_t)AKV_W * 4u;

    const int tid = threadIdx.x;
    const int wid = tid >> 5;
    const int lane = tid & 31;
    const int g = lane >> 2;
    const int t = lane & 3;
    const int qb = blockIdx.x;               // 0..31 (64-row q tiles)
    const int hp = blockIdx.y;               // head pair 0..15
    const int b  = blockIdx.z;
    const int hh = wid >> 2;                 // head in pair 0/1
    const int ws = wid & 3;                  // row subtile 0..3
    const int h  = hp * 2 + hh;
    const int kvh = h >> 2;

    const uint32_t* Kbase  = Kh + (size_t)(b * SEQ) * (KVDIM / 2) + kvh * (HDIM / 2);
    const uint32_t* Vtbase = Vth + (size_t)((b * NKV + kvh) * HDIM) * (SEQ / 2);

    const uint32_t bl_off =
        (uint32_t)((((lane & 7) + ((lane >> 4) & 1) * 8) * 36 + ((lane >> 3) & 1) * 4) * 4);

    // K/Vt tile fill: 2 cp.async per thread = 512 ops/tile (R11 pattern)
    auto issue = [&](int jb, int s) {
#pragma unroll
        for (int j = 0; j < 2; j++) {
            int idx = j * 256 + tid;
            int r = idx >> 3, c4 = (idx & 7) * 4;
            uint32_t so = (uint32_t)(s * AKV_W + r * 36 + c4) * 4u;
            cpasync16(sbase + ks_off + so, Kbase + (size_t)(jb * 64 + r) * (KVDIM / 2) + c4);
            cpasync16(sbase + vt_off + so, Vtbase + (size_t)r * (SEQ / 2) + jb * 32 + c4);
        }
        asm volatile("cp.async.commit_group;" ::: "memory");
    };

    issue(0, 0);

    // Stage Q tile: 64 rows x 64 u32 (2 adjacent heads), scale by 1/8.
    {
        const __half2 sc = __float2half2_rn(0.125f);
        const uint32_t* src = Qh + (size_t)(b * SEQ + qb * 64) * (HIDDEN / 2) + hp * 64;
#pragma unroll
        for (int j = 0; j < 4; j++) {
            int idx = j * 256 + tid;
            int r = idx >> 4, c = (idx & 15) * 4;
            uint4 v = *(const uint4*)(src + (size_t)r * (HIDDEN / 2) + c);
            __half2* hx = (__half2*)&v;
            hx[0] = __hmul2(hx[0], sc); hx[1] = __hmul2(hx[1], sc);
            hx[2] = __hmul2(hx[2], sc); hx[3] = __hmul2(hx[3], sc);
            uint32_t* dst = &Qs[r * 68 + c];
            dst[0] = v.x; dst[1] = v.y; dst[2] = v.z; dst[3] = v.w;
        }
    }
    __syncthreads();

    // Hoist Q fragments (loop-invariant). Row: ws*16 + g; head cols: hh*32.
    const int qr = ws * 16 + g;
    const int qc0 = hh * 32;
    uint32_t qf[4][4];
#pragma unroll
    for (int kk = 0; kk < 4; kk++) {
        const int kc = qc0 + kk * 8 + t;
        qf[kk][0] = Qs[qr * 68 + kc];
        qf[kk][1] = Qs[(qr + 8) * 68 + kc];
        qf[kk][2] = Qs[qr * 68 + kc + 4];
        qf[kk][3] = Qs[(qr + 8) * 68 + kc + 4];
    }

    float acc_o[8][4] = {};
    float m0 = -1e30f, m1 = -1e30f, l0 = 0.f, l1 = 0.f;

    for (int jb = 0; jb < SEQ / 64; jb++) {
        const int s = jb & 1;
        if (jb + 1 < SEQ / 64) {
            issue(jb + 1, s ^ 1);
            asm volatile("cp.async.wait_group %0;" :: "n"(1) : "memory");
        } else {
            asm volatile("cp.async.wait_group %0;" :: "n"(0) : "memory");
        }
        __syncthreads();

        const uint32_t kf_base = sbase + ks_off + (uint32_t)(s * AKV_W) * 4u + bl_off;
        const uint32_t vf_base = sbase + vt_off + (uint32_t)(s * AKV_W) * 4u + bl_off;

        // S = Q K^T
        float acc_s[8][4] = {};
#pragma unroll
        for (int kk = 0; kk < 4; kk++) {
            const uint32_t ko = (uint32_t)(kk * 8) * 4u;
#pragma unroll
            for (int p = 0; p < 4; p++) {
                uint32_t bf[4];
                LDSM4(bf[0], bf[1], bf[2], bf[3], kf_base + ko + (uint32_t)(p * 16 * 36) * 4u);
                mma_f16(acc_s[2*p],     qf[kk], bf);
                mma_f16(acc_s[2*p + 1], qf[kk], bf + 2);
            }
        }

        // Fragment online softmax
        float mx0 = -1e30f, mx1 = -1e30f;
#pragma unroll
        for (int ni = 0; ni < 8; ni++) {
            mx0 = fmaxf(mx0, fmaxf(acc_s[ni][0], acc_s[ni][1]));
            mx1 = fmaxf(mx1, fmaxf(acc_s[ni][2], acc_s[ni][3]));
        }
        mx0 = fmaxf(mx0, __shfl_xor_sync(0xffffffffu, mx0, 1));
        mx0 = fmaxf(mx0, __shfl_xor_sync(0xffffffffu, mx0, 2));
        mx1 = fmaxf(mx1, __shfl_xor_sync(0xffffffffu, mx1, 1));
        mx1 = fmaxf(mx1, __shfl_xor_sync(0xffffffffu, mx1, 2));
        const float mn0 = fmaxf(m0, mx0);
        const float mn1 = fmaxf(m1, mx1);
        const float sf0 = __expf(m0 - mn0);
        const float sf1 = __expf(m1 - mn1);
        m0 = mn0; m1 = mn1;

#pragma unroll
        for (int dn = 0; dn < 8; dn++) {
            acc_o[dn][0] *= sf0; acc_o[dn][1] *= sf0;
            acc_o[dn][2] *= sf1; acc_o[dn][3] *= sf1;
        }

        // P = exp(S - m): pack directly into PV A-fragments
        uint32_t pf[4][4];
        float rs0 = 0.f, rs1 = 0.f;
#pragma unroll
        for (int kb = 0; kb < 4; kb++) {
#pragma unroll
            for (int half = 0; half < 2; half++) {
                const int ni = 2 * kb + half;
                float p0 = __expf(acc_s[ni][0] - mn0);
                float p1 = __expf(acc_s[ni][1] - mn0);
                float p2 = __expf(acc_s[ni][2] - mn1);
                float p3 = __expf(acc_s[ni][3] - mn1);
                rs0 += p0 + p1;
                rs1 += p2 + p3;
                __half2 w0 = __floats2half2_rn(p0, p1);
                __half2 w1 = __floats2half2_rn(p2, p3);
                pf[kb][half * 2 + 0] = *(uint32_t*)&w0;
                pf[kb][half * 2 + 1] = *(uint32_t*)&w1;
            }
        }
        rs0 += __shfl_xor_sync(0xffffffffu, rs0, 1);
        rs0 += __shfl_xor_sync(0xffffffffu, rs0, 2);
        rs1 += __shfl_xor_sync(0xffffffffu, rs1, 1);
        rs1 += __shfl_xor_sync(0xffffffffu, rs1, 2);
        l0 = l0 * sf0 + rs0;
        l1 = l1 * sf1 + rs1;

        // O += P V
#pragma unroll
        for (int kb = 0; kb < 4; kb++) {
            const uint32_t ko = (uint32_t)(kb * 8) * 4u;
#pragma unroll
            for (int p = 0; p < 4; p++) {
                uint32_t bf[4];
                LDSM4(bf[0], bf[1], bf[2], bf[3], vf_base + ko + (uint32_t)(p * 16 * 36) * 4u);
                mma_f16(acc_o[2*p],     pf[kb], bf);
                mma_f16(acc_o[2*p + 1], pf[kb], bf + 2);
            }
        }
        __syncthreads();
    }

    // Epilogue: normalize, store fp16 (feeds O-proj mma)
    const float i0 = 1.f / l0;
    const float i1 = 1.f / l1;
    const int row0 = b * SEQ + qb * 64 + qr;
#pragma unroll
    for (int dn = 0; dn < 8; dn++) {
        const int cp = h * (HDIM / 2) + dn * 4 + t;
        __half2 h0 = __floats2half2_rn(acc_o[dn][0] * i0, acc_o[dn][1] * i0);
        __half2 h1 = __floats2half2_rn(acc_o[dn][2] * i1, acc_o[dn][3] * i1);
        Oh[(size_t)row0 * (HIDDEN / 2) + cp] = *(uint32_t*)&h0;
        Oh[(size_t)(row0 + 8) * (HIDDEN / 2) + cp] = *(uint32_t*)&h1;
    }
}

// ---------------------------------------------------------------------------
extern "C" void kernel_launch(void* const* d_in, const int* in_sizes, int n_in,
                              void* d_out, int out_size)
{
    const float* x  = (const float*)d_in[0];
    const float* wq = (const float*)d_in[1];
    const float* bq = (const float*)d_in[2];
    const float* wk = (const float*)d_in[3];
    const float* bk = (const float*)d_in[4];
    const float* wv = (const float*)d_in[5];
    const float* bv = (const float*)d_in[6];
    const float* wo = (const float*)d_in[7];
    const float* bo = (const float*)d_in[8];
    float* out = (float*)d_out;

    __half *xh, *wqkvh, *woh, *qh, *kh, *vt, *oh;
    cudaGetSymbolAddress((void**)&xh, g_xh);
    cudaGetSymbolAddress((void**)&wqkvh, g_wqkvh);
    cudaGetSymbolAddress((void**)&woh, g_woh);
    cudaGetSymbolAddress((void**)&qh, g_qh);
    cudaGetSymbolAddress((void**)&kh, g_kh);
    cudaGetSymbolAddress((void**)&vt, g_vt);
    cudaGetSymbolAddress((void**)&oh, g_oh);

    cudaFuncSetAttribute(gemm_qkv,   cudaFuncAttributeMaxDynamicSharedMemorySize, GSM_BYTES);
    cudaFuncSetAttribute(gemm_oproj, cudaFuncAttributeMaxDynamicSharedMemorySize, GSM_BYTES);
    cudaFuncSetAttribute(attn_mma,   cudaFuncAttributeMaxDynamicSharedMemorySize, ASM_BYTES);

    cvt_all<<<(TOT4 + 255) / 256, 256>>>(
        (const float4*)x, (const float4*)wq, (const float4*)wk,
        (const float4*)wv, (const float4*)wo,
        (uint2*)xh, (uint2*)wqkvh, (uint2*)woh);

    gemm_qkv<<<dim3(NQKV / 256, MROWS / 128), 512, GSM_BYTES>>>(
        (const uint32_t*)xh, (const uint32_t*)wqkvh, bq, bk, bv,
        (uint32_t*)qh, (uint32_t*)kh, vt);

    attn_mma<<<dim3(SEQ / 64, NHEADS / 2, BATCH), 256, ASM_BYTES>>>(
        (const uint32_t*)qh, (const uint32_t*)kh, (const uint32_t*)vt, (uint32_t*)oh);

    gemm_oproj<<<dim3(HIDDEN / 256, MROWS / 128), 512, GSM_BYTES>>>(
        (const uint32_t*)oh, (const uint32_t*)woh, bo, out);
}